// round 1
// baseline (speedup 1.0000x reference)
#include <cuda_runtime.h>
#include <math.h>

#define BB 2
#define NN 2048
#define EE 1024
#define HH 8
#define DD 64
#define DV 128
#define KPAD 68
#define VPAD 132

// Scratch (no runtime allocation allowed)
__device__ float g_q[BB * NN * EE];
__device__ float g_k[BB * NN * EE];
__device__ float g_v[BB * NN * EE];
__device__ float g_att[BB * NN * EE];
__device__ float g_lambda;

// ---------------------------------------------------------------------------
// lambda = exp(lq1.lk1) - exp(lq2.lk2) + (0.8 - 0.6*exp(-0.3*12))
// ---------------------------------------------------------------------------
__global__ void lambda_kernel(const float* __restrict__ lq1, const float* __restrict__ lk1,
                              const float* __restrict__ lq2, const float* __restrict__ lk2) {
    int t = threadIdx.x;
    float s1 = 0.f, s2 = 0.f;
    for (int i = t; i < DD; i += 32) {
        s1 += lq1[i] * lk1[i];
        s2 += lq2[i] * lk2[i];
    }
#pragma unroll
    for (int o = 16; o; o >>= 1) {
        s1 += __shfl_xor_sync(0xffffffffu, s1, o);
        s2 += __shfl_xor_sync(0xffffffffu, s2, o);
    }
    if (t == 0) {
        double lam_init = 0.8 - 0.6 * exp(-0.3 * 12.0);
        g_lambda = expf(s1) - expf(s2) + (float)lam_init;
    }
}

// ---------------------------------------------------------------------------
// SGEMM: C[M,N] = alpha * A[M,K] @ B[K,N], all row-major fp32.
// 128x128 tile, BK=8, 256 threads, 8x8 microtile.
// ---------------------------------------------------------------------------
__global__ __launch_bounds__(256) void sgemm_kernel(const float* __restrict__ A,
                                                    const float* __restrict__ B,
                                                    float* __restrict__ C,
                                                    int M, int N, int K, float alpha) {
    __shared__ float sA[8][128];
    __shared__ float sB[8][128];
    const int tid = threadIdx.x;
    const int tr = tid >> 4, tc = tid & 15;
    const int rowBase = blockIdx.y << 7;
    const int colBase = blockIdx.x << 7;
    const int aRow = tid >> 1, aCol = (tid & 1) << 2;
    const int bRow = tid >> 5, bCol = (tid & 31) << 2;
    const float* Ap = A + (size_t)(rowBase + aRow) * K + aCol;
    const float* Bp = B + (size_t)bRow * N + colBase + bCol;

    float acc[8][8];
#pragma unroll
    for (int i = 0; i < 8; ++i)
#pragma unroll
        for (int j = 0; j < 8; ++j) acc[i][j] = 0.f;

    for (int kt = 0; kt < K; kt += 8) {
        float4 av = *(const float4*)(Ap + kt);
        float4 bv = *(const float4*)(Bp + (size_t)kt * N);
        sA[aCol + 0][aRow] = av.x;
        sA[aCol + 1][aRow] = av.y;
        sA[aCol + 2][aRow] = av.z;
        sA[aCol + 3][aRow] = av.w;
        *(float4*)&sB[bRow][bCol] = bv;
        __syncthreads();
#pragma unroll
        for (int kk = 0; kk < 8; ++kk) {
            float a[8], b[8];
            *(float4*)&a[0] = *(const float4*)&sA[kk][tr * 8];
            *(float4*)&a[4] = *(const float4*)&sA[kk][tr * 8 + 4];
            *(float4*)&b[0] = *(const float4*)&sB[kk][tc * 8];
            *(float4*)&b[4] = *(const float4*)&sB[kk][tc * 8 + 4];
#pragma unroll
            for (int i = 0; i < 8; ++i)
#pragma unroll
                for (int j = 0; j < 8; ++j) acc[i][j] += a[i] * b[j];
        }
        __syncthreads();
    }
#pragma unroll
    for (int i = 0; i < 8; ++i) {
        float* Cp = C + (size_t)(rowBase + tr * 8 + i) * N + colBase + tc * 8;
        float4 v0, v1;
        v0.x = alpha * acc[i][0]; v0.y = alpha * acc[i][1];
        v0.z = alpha * acc[i][2]; v0.w = alpha * acc[i][3];
        v1.x = alpha * acc[i][4]; v1.y = alpha * acc[i][5];
        v1.z = alpha * acc[i][6]; v1.w = alpha * acc[i][7];
        *(float4*)Cp = v0;
        *(float4*)(Cp + 4) = v1;
    }
}

// ---------------------------------------------------------------------------
// Differential flash attention + fused per-head LayerNorm.
// One CTA: batch b, head-pair h (half-heads 2h, 2h+1), 32 q rows.
// 128 threads laid out 8(ty) x 16(tx): thread owns 4 q-rows (ty*4..),
// 4 score cols (tx*4..) during S, 8 output cols (tx*8..) during PV.
// ---------------------------------------------------------------------------
__device__ __forceinline__ float dot4(float4 a, float4 b) {
    return a.x * b.x + a.y * b.y + a.z * b.z + a.w * b.w;
}
__device__ __forceinline__ void fma4(float4& a, float s, float4 b) {
    a.x += s * b.x; a.y += s * b.y; a.z += s * b.z; a.w += s * b.w;
}
__device__ __forceinline__ void mul4(float4& a, float s) {
    a.x *= s; a.y *= s; a.z *= s; a.w *= s;
}

__global__ __launch_bounds__(128) void flash_kernel(const float* __restrict__ q,
                                                    const float* __restrict__ k,
                                                    const float* __restrict__ v,
                                                    const float* __restrict__ lng,
                                                    const float* __restrict__ lnb,
                                                    float* __restrict__ out) {
    extern __shared__ float sm[];
    float* sQ0 = sm;                    // 32*64
    float* sQ1 = sQ0 + 32 * 64;        // 32*64
    float* sK0 = sQ1 + 32 * 64;        // 64*KPAD
    float* sK1 = sK0 + 64 * KPAD;      // 64*KPAD
    float* sV  = sK1 + 64 * KPAD;      // 64*VPAD
    float* sP0 = sV + 64 * VPAD;       // 32*KPAD
    float* sP1 = sP0 + 32 * KPAD;      // 32*KPAD

    const int tid = threadIdx.x;
    const int ty = tid >> 4, tx = tid & 15;
    const int b = blockIdx.z, h = blockIdx.y;
    const int qbase = blockIdx.x * 32;
    const float lam = g_lambda;

    // Load Q tiles (both half-heads), already scaled by D^-0.5 in projection.
#pragma unroll
    for (int t = 0; t < 4; ++t) {
        int idx = tid + t * 128;
        int r = idx >> 4, o = (idx & 15) << 2;
        const float* src = q + ((size_t)(b * NN + qbase + r)) * EE + 2 * h * DD;
        *(float4*)&sQ0[r * 64 + o] = *(const float4*)(src + o);
        *(float4*)&sQ1[r * 64 + o] = *(const float4*)(src + DD + o);
    }

    float m0[4], l0[4], m1[4], l1[4];
    float4 a0[4][2], a1[4][2];
#pragma unroll
    for (int i = 0; i < 4; ++i) {
        m0[i] = m1[i] = -INFINITY;
        l0[i] = l1[i] = 0.f;
        a0[i][0] = a0[i][1] = make_float4(0.f, 0.f, 0.f, 0.f);
        a1[i][0] = a1[i][1] = make_float4(0.f, 0.f, 0.f, 0.f);
    }

    for (int kt = 0; kt < NN; kt += 64) {
        __syncthreads();  // previous PV done before overwriting K/V
        // Load K tiles for both half-heads (64x64 each)
#pragma unroll
        for (int t = 0; t < 8; ++t) {
            int idx = tid + t * 128;
            int r = idx >> 4, o = (idx & 15) << 2;
            const float* src = k + ((size_t)(b * NN + kt + r)) * EE + 2 * h * DD;
            *(float4*)&sK0[r * KPAD + o] = *(const float4*)(src + o);
            *(float4*)&sK1[r * KPAD + o] = *(const float4*)(src + DD + o);
        }
        // Load V tile (64 x 128), shared by the pair
#pragma unroll
        for (int t = 0; t < 16; ++t) {
            int idx = tid + t * 128;
            int r = idx >> 5, o = (idx & 31) << 2;
            const float* src = v + ((size_t)(b * NN + kt + r)) * EE + h * DV;
            *(float4*)&sV[r * VPAD + o] = *(const float4*)(src + o);
        }
        __syncthreads();

        // S = Q @ K^T for both half-heads: 4x4 microtile per thread
        float s0[4][4], s1t[4][4];
#pragma unroll
        for (int i = 0; i < 4; ++i)
#pragma unroll
            for (int j = 0; j < 4; ++j) { s0[i][j] = 0.f; s1t[i][j] = 0.f; }
#pragma unroll
        for (int k4 = 0; k4 < 16; ++k4) {
            float4 qa0[4], qa1[4], kb0[4], kb1[4];
#pragma unroll
            for (int i = 0; i < 4; ++i) {
                qa0[i] = *(const float4*)&sQ0[(ty * 4 + i) * 64 + k4 * 4];
                qa1[i] = *(const float4*)&sQ1[(ty * 4 + i) * 64 + k4 * 4];
            }
#pragma unroll
            for (int j = 0; j < 4; ++j) {
                kb0[j] = *(const float4*)&sK0[(tx * 4 + j) * KPAD + k4 * 4];
                kb1[j] = *(const float4*)&sK1[(tx * 4 + j) * KPAD + k4 * 4];
            }
#pragma unroll
            for (int i = 0; i < 4; ++i)
#pragma unroll
                for (int j = 0; j < 4; ++j) {
                    s0[i][j] += dot4(qa0[i], kb0[j]);
                    s1t[i][j] += dot4(qa1[i], kb1[j]);
                }
        }

        // Online softmax (row state replicated across the 16 lanes of a row group)
#pragma unroll
        for (int i = 0; i < 4; ++i) {
            float rm0 = fmaxf(fmaxf(s0[i][0], s0[i][1]), fmaxf(s0[i][2], s0[i][3]));
            float rm1 = fmaxf(fmaxf(s1t[i][0], s1t[i][1]), fmaxf(s1t[i][2], s1t[i][3]));
#pragma unroll
            for (int o = 8; o; o >>= 1) {
                rm0 = fmaxf(rm0, __shfl_xor_sync(0xffffffffu, rm0, o));
                rm1 = fmaxf(rm1, __shfl_xor_sync(0xffffffffu, rm1, o));
            }
            float mn0 = fmaxf(m0[i], rm0), mn1 = fmaxf(m1[i], rm1);
            float al0 = __expf(m0[i] - mn0), al1 = __expf(m1[i] - mn1);
            float rs0 = 0.f, rs1 = 0.f;
#pragma unroll
            for (int j = 0; j < 4; ++j) {
                float p0 = __expf(s0[i][j] - mn0);
                float p1 = __expf(s1t[i][j] - mn1);
                sP0[(ty * 4 + i) * KPAD + tx * 4 + j] = p0;
                sP1[(ty * 4 + i) * KPAD + tx * 4 + j] = p1;
                rs0 += p0; rs1 += p1;
            }
#pragma unroll
            for (int o = 8; o; o >>= 1) {
                rs0 += __shfl_xor_sync(0xffffffffu, rs0, o);
                rs1 += __shfl_xor_sync(0xffffffffu, rs1, o);
            }
            l0[i] = l0[i] * al0 + rs0; m0[i] = mn0;
            l1[i] = l1[i] * al1 + rs1; m1[i] = mn1;
            mul4(a0[i][0], al0); mul4(a0[i][1], al0);
            mul4(a1[i][0], al1); mul4(a1[i][1], al1);
        }
        __syncthreads();  // sP visible to all before PV

        // acc += P @ V (both half-heads share V)
#pragma unroll
        for (int c4 = 0; c4 < 16; ++c4) {
            float4 va[4][2];
#pragma unroll
            for (int cc = 0; cc < 4; ++cc) {
                va[cc][0] = *(const float4*)&sV[(c4 * 4 + cc) * VPAD + tx * 8];
                va[cc][1] = *(const float4*)&sV[(c4 * 4 + cc) * VPAD + tx * 8 + 4];
            }
#pragma unroll
            for (int i = 0; i < 4; ++i) {
                float4 p0 = *(const float4*)&sP0[(ty * 4 + i) * KPAD + c4 * 4];
                float4 p1 = *(const float4*)&sP1[(ty * 4 + i) * KPAD + c4 * 4];
                float pv0[4] = {p0.x, p0.y, p0.z, p0.w};
                float pv1[4] = {p1.x, p1.y, p1.z, p1.w};
#pragma unroll
                for (int cc = 0; cc < 4; ++cc) {
                    fma4(a0[i][0], pv0[cc], va[cc][0]);
                    fma4(a0[i][1], pv0[cc], va[cc][1]);
                    fma4(a1[i][0], pv1[cc], va[cc][0]);
                    fma4(a1[i][1], pv1[cc], va[cc][1]);
                }
            }
        }
    }

    // Epilogue: o = acc0/l0 - lam*acc1/l1, then per-head LayerNorm over 128.
    float4 gv0 = *(const float4*)&lng[tx * 8];
    float4 gv1 = *(const float4*)&lng[tx * 8 + 4];
    float4 bv0 = *(const float4*)&lnb[tx * 8];
    float4 bv1 = *(const float4*)&lnb[tx * 8 + 4];
#pragma unroll
    for (int i = 0; i < 4; ++i) {
        float il0 = 1.f / l0[i];
        float il1 = lam / l1[i];
        float o8[8];
        o8[0] = a0[i][0].x * il0 - a1[i][0].x * il1;
        o8[1] = a0[i][0].y * il0 - a1[i][0].y * il1;
        o8[2] = a0[i][0].z * il0 - a1[i][0].z * il1;
        o8[3] = a0[i][0].w * il0 - a1[i][0].w * il1;
        o8[4] = a0[i][1].x * il0 - a1[i][1].x * il1;
        o8[5] = a0[i][1].y * il0 - a1[i][1].y * il1;
        o8[6] = a0[i][1].z * il0 - a1[i][1].z * il1;
        o8[7] = a0[i][1].w * il0 - a1[i][1].w * il1;
        float s = 0.f, s2 = 0.f;
#pragma unroll
        for (int jj = 0; jj < 8; ++jj) { s += o8[jj]; s2 += o8[jj] * o8[jj]; }
#pragma unroll
        for (int o = 8; o; o >>= 1) {
            s += __shfl_xor_sync(0xffffffffu, s, o);
            s2 += __shfl_xor_sync(0xffffffffu, s2, o);
        }
        float mu = s * (1.f / 128.f);
        float var = s2 * (1.f / 128.f) - mu * mu;
        float rstd = rsqrtf(var + 1e-5f);
        float g8[8] = {gv0.x, gv0.y, gv0.z, gv0.w, gv1.x, gv1.y, gv1.z, gv1.w};
        float b8[8] = {bv0.x, bv0.y, bv0.z, bv0.w, bv1.x, bv1.y, bv1.z, bv1.w};
        float y[8];
#pragma unroll
        for (int jj = 0; jj < 8; ++jj) y[jj] = (o8[jj] - mu) * rstd * g8[jj] + b8[jj];
        float* dst = out + ((size_t)(b * NN + qbase + ty * 4 + i)) * EE + h * DV + tx * 8;
        *(float4*)dst = make_float4(y[0], y[1], y[2], y[3]);
        *(float4*)(dst + 4) = make_float4(y[4], y[5], y[6], y[7]);
    }
}

// ---------------------------------------------------------------------------
extern "C" void kernel_launch(void* const* d_in, const int* in_sizes, int n_in,
                              void* d_out, int out_size) {
    const float* x   = (const float*)d_in[0];
    const float* Wq  = (const float*)d_in[1];
    const float* Wk  = (const float*)d_in[2];
    const float* Wv  = (const float*)d_in[3];
    const float* Wo  = (const float*)d_in[4];
    const float* lq1 = (const float*)d_in[5];
    const float* lk1 = (const float*)d_in[6];
    const float* lq2 = (const float*)d_in[7];
    const float* lk2 = (const float*)d_in[8];
    const float* lng = (const float*)d_in[9];
    const float* lnb = (const float*)d_in[10];
    float* out = (float*)d_out;

    float *qp, *kp, *vp, *ap;
    cudaGetSymbolAddress((void**)&qp, g_q);
    cudaGetSymbolAddress((void**)&kp, g_k);
    cudaGetSymbolAddress((void**)&vp, g_v);
    cudaGetSymbolAddress((void**)&ap, g_att);

    const int M = BB * NN;  // 4096
    dim3 gg(EE / 128, M / 128);  // (8, 32)

    sgemm_kernel<<<gg, 256>>>(x, Wq, qp, M, EE, EE, 0.125f);  // q * D^-0.5
    sgemm_kernel<<<gg, 256>>>(x, Wk, kp, M, EE, EE, 1.f);
    sgemm_kernel<<<gg, 256>>>(x, Wv, vp, M, EE, EE, 1.f);
    lambda_kernel<<<1, 32>>>(lq1, lk1, lq2, lk2);

    int smem = (32 * 64 * 2 + 64 * KPAD * 2 + 64 * VPAD + 32 * KPAD * 2) * 4;  // 102400 B
    cudaFuncSetAttribute(flash_kernel, cudaFuncAttributeMaxDynamicSharedMemorySize, smem);
    dim3 fg(NN / 32, HH, BB);  // (64, 8, 2)
    flash_kernel<<<fg, 128, smem>>>(qp, kp, vp, lng, lnb, ap);

    sgemm_kernel<<<gg, 256>>>(ap, Wo, out, M, EE, EE, 1.f);
}

// round 2
// speedup vs baseline: 1.0021x; 1.0021x over previous
#include <cuda_runtime.h>
#include <math.h>

#define BB 2
#define NN 2048
#define EE 1024
#define HH 8
#define DD 64
#define DV 128
#define KPAD 68
#define VPAD 132

// Scratch (no runtime allocation allowed)
__device__ float g_q[BB * NN * EE];
__device__ float g_k[BB * NN * EE];
__device__ float g_v[BB * NN * EE];
__device__ float g_att[BB * NN * EE];
__device__ float g_lambda;

// ---------------------------------------------------------------------------
// lambda = exp(lq1.lk1) - exp(lq2.lk2) + (0.8 - 0.6*exp(-0.3*12))
// ---------------------------------------------------------------------------
__global__ void lambda_kernel(const float* __restrict__ lq1, const float* __restrict__ lk1,
                              const float* __restrict__ lq2, const float* __restrict__ lk2) {
    int t = threadIdx.x;
    float s1 = 0.f, s2 = 0.f;
    for (int i = t; i < DD; i += 32) {
        s1 += lq1[i] * lk1[i];
        s2 += lq2[i] * lk2[i];
    }
#pragma unroll
    for (int o = 16; o; o >>= 1) {
        s1 += __shfl_xor_sync(0xffffffffu, s1, o);
        s2 += __shfl_xor_sync(0xffffffffu, s2, o);
    }
    if (t == 0) {
        double lam_init = 0.8 - 0.6 * exp(-0.3 * 12.0);
        g_lambda = expf(s1) - expf(s2) + (float)lam_init;
    }
}

// ---------------------------------------------------------------------------
// SGEMM: C[M,N] = alpha * A[M,K] @ B[K,N], all row-major fp32.
// 128x128 tile, BK=8, 256 threads, 8x8 microtile.
// ---------------------------------------------------------------------------
__global__ __launch_bounds__(256) void sgemm_kernel(const float* __restrict__ A,
                                                    const float* __restrict__ B,
                                                    float* __restrict__ C,
                                                    int M, int N, int K, float alpha) {
    __shared__ float sA[8][128];
    __shared__ float sB[8][128];
    const int tid = threadIdx.x;
    const int tr = tid >> 4, tc = tid & 15;
    const int rowBase = blockIdx.y << 7;
    const int colBase = blockIdx.x << 7;
    const int aRow = tid >> 1, aCol = (tid & 1) << 2;
    const int bRow = tid >> 5, bCol = (tid & 31) << 2;
    const float* Ap = A + (size_t)(rowBase + aRow) * K + aCol;
    const float* Bp = B + (size_t)bRow * N + colBase + bCol;

    float acc[8][8];
#pragma unroll
    for (int i = 0; i < 8; ++i)
#pragma unroll
        for (int j = 0; j < 8; ++j) acc[i][j] = 0.f;

    for (int kt = 0; kt < K; kt += 8) {
        float4 av = *(const float4*)(Ap + kt);
        float4 bv = *(const float4*)(Bp + (size_t)kt * N);
        sA[aCol + 0][aRow] = av.x;
        sA[aCol + 1][aRow] = av.y;
        sA[aCol + 2][aRow] = av.z;
        sA[aCol + 3][aRow] = av.w;
        *(float4*)&sB[bRow][bCol] = bv;
        __syncthreads();
#pragma unroll
        for (int kk = 0; kk < 8; ++kk) {
            float a[8], b[8];
            *(float4*)&a[0] = *(const float4*)&sA[kk][tr * 8];
            *(float4*)&a[4] = *(const float4*)&sA[kk][tr * 8 + 4];
            *(float4*)&b[0] = *(const float4*)&sB[kk][tc * 8];
            *(float4*)&b[4] = *(const float4*)&sB[kk][tc * 8 + 4];
#pragma unroll
            for (int i = 0; i < 8; ++i)
#pragma unroll
                for (int j = 0; j < 8; ++j) acc[i][j] += a[i] * b[j];
        }
        __syncthreads();
    }
#pragma unroll
    for (int i = 0; i < 8; ++i) {
        float* Cp = C + (size_t)(rowBase + tr * 8 + i) * N + colBase + tc * 8;
        float4 v0, v1;
        v0.x = alpha * acc[i][0]; v0.y = alpha * acc[i][1];
        v0.z = alpha * acc[i][2]; v0.w = alpha * acc[i][3];
        v1.x = alpha * acc[i][4]; v1.y = alpha * acc[i][5];
        v1.z = alpha * acc[i][6]; v1.w = alpha * acc[i][7];
        *(float4*)Cp = v0;
        *(float4*)(Cp + 4) = v1;
    }
}

// ---------------------------------------------------------------------------
// Differential flash attention + fused per-head LayerNorm.
// One CTA: batch b, head-pair h (half-heads 2h, 2h+1), 32 q rows.
// 128 threads laid out 8(ty) x 16(tx): thread owns 4 q-rows (ty*4..),
// 4 score cols (tx*4..) during S, 8 output cols (tx*8..) during PV.
// ---------------------------------------------------------------------------
__device__ __forceinline__ float dot4(float4 a, float4 b) {
    return a.x * b.x + a.y * b.y + a.z * b.z + a.w * b.w;
}
__device__ __forceinline__ void fma4(float4& a, float s, float4 b) {
    a.x += s * b.x; a.y += s * b.y; a.z += s * b.z; a.w += s * b.w;
}
__device__ __forceinline__ void mul4(float4& a, float s) {
    a.x *= s; a.y *= s; a.z *= s; a.w *= s;
}

__global__ __launch_bounds__(128) void flash_kernel(const float* __restrict__ q,
                                                    const float* __restrict__ k,
                                                    const float* __restrict__ v,
                                                    const float* __restrict__ lng,
                                                    const float* __restrict__ lnb,
                                                    float* __restrict__ out) {
    extern __shared__ float sm[];
    float* sQ0 = sm;                    // 32*64
    float* sQ1 = sQ0 + 32 * 64;        // 32*64
    float* sK0 = sQ1 + 32 * 64;        // 64*KPAD
    float* sK1 = sK0 + 64 * KPAD;      // 64*KPAD
    float* sV  = sK1 + 64 * KPAD;      // 64*VPAD
    float* sP0 = sV + 64 * VPAD;       // 32*KPAD
    float* sP1 = sP0 + 32 * KPAD;      // 32*KPAD

    const int tid = threadIdx.x;
    const int ty = tid >> 4, tx = tid & 15;
    const int b = blockIdx.z, h = blockIdx.y;
    const int qbase = blockIdx.x * 32;
    const float lam = g_lambda;

    // Load Q tiles (both half-heads), already scaled by D^-0.5 in projection.
#pragma unroll
    for (int t = 0; t < 4; ++t) {
        int idx = tid + t * 128;
        int r = idx >> 4, o = (idx & 15) << 2;
        const float* src = q + ((size_t)(b * NN + qbase + r)) * EE + 2 * h * DD;
        *(float4*)&sQ0[r * 64 + o] = *(const float4*)(src + o);
        *(float4*)&sQ1[r * 64 + o] = *(const float4*)(src + DD + o);
    }

    float m0[4], l0[4], m1[4], l1[4];
    float4 a0[4][2], a1[4][2];
#pragma unroll
    for (int i = 0; i < 4; ++i) {
        m0[i] = m1[i] = -INFINITY;
        l0[i] = l1[i] = 0.f;
        a0[i][0] = a0[i][1] = make_float4(0.f, 0.f, 0.f, 0.f);
        a1[i][0] = a1[i][1] = make_float4(0.f, 0.f, 0.f, 0.f);
    }

    for (int kt = 0; kt < NN; kt += 64) {
        __syncthreads();  // previous PV done before overwriting K/V
        // Load K tiles for both half-heads (64x64 each)
#pragma unroll
        for (int t = 0; t < 8; ++t) {
            int idx = tid + t * 128;
            int r = idx >> 4, o = (idx & 15) << 2;
            const float* src = k + ((size_t)(b * NN + kt + r)) * EE + 2 * h * DD;
            *(float4*)&sK0[r * KPAD + o] = *(const float4*)(src + o);
            *(float4*)&sK1[r * KPAD + o] = *(const float4*)(src + DD + o);
        }
        // Load V tile (64 x 128), shared by the pair
#pragma unroll
        for (int t = 0; t < 16; ++t) {
            int idx = tid + t * 128;
            int r = idx >> 5, o = (idx & 31) << 2;
            const float* src = v + ((size_t)(b * NN + kt + r)) * EE + h * DV;
            *(float4*)&sV[r * VPAD + o] = *(const float4*)(src + o);
        }
        __syncthreads();

        // S = Q @ K^T for both half-heads: 4x4 microtile per thread
        float s0[4][4], s1t[4][4];
#pragma unroll
        for (int i = 0; i < 4; ++i)
#pragma unroll
            for (int j = 0; j < 4; ++j) { s0[i][j] = 0.f; s1t[i][j] = 0.f; }
#pragma unroll
        for (int k4 = 0; k4 < 16; ++k4) {
            float4 qa0[4], qa1[4], kb0[4], kb1[4];
#pragma unroll
            for (int i = 0; i < 4; ++i) {
                qa0[i] = *(const float4*)&sQ0[(ty * 4 + i) * 64 + k4 * 4];
                qa1[i] = *(const float4*)&sQ1[(ty * 4 + i) * 64 + k4 * 4];
            }
#pragma unroll
            for (int j = 0; j < 4; ++j) {
                kb0[j] = *(const float4*)&sK0[(tx * 4 + j) * KPAD + k4 * 4];
                kb1[j] = *(const float4*)&sK1[(tx * 4 + j) * KPAD + k4 * 4];
            }
#pragma unroll
            for (int i = 0; i < 4; ++i)
#pragma unroll
                for (int j = 0; j < 4; ++j) {
                    s0[i][j] += dot4(qa0[i], kb0[j]);
                    s1t[i][j] += dot4(qa1[i], kb1[j]);
                }
        }

        // Online softmax (row state replicated across the 16 lanes of a row group)
#pragma unroll
        for (int i = 0; i < 4; ++i) {
            float rm0 = fmaxf(fmaxf(s0[i][0], s0[i][1]), fmaxf(s0[i][2], s0[i][3]));
            float rm1 = fmaxf(fmaxf(s1t[i][0], s1t[i][1]), fmaxf(s1t[i][2], s1t[i][3]));
#pragma unroll
            for (int o = 8; o; o >>= 1) {
                rm0 = fmaxf(rm0, __shfl_xor_sync(0xffffffffu, rm0, o));
                rm1 = fmaxf(rm1, __shfl_xor_sync(0xffffffffu, rm1, o));
            }
            float mn0 = fmaxf(m0[i], rm0), mn1 = fmaxf(m1[i], rm1);
            float al0 = __expf(m0[i] - mn0), al1 = __expf(m1[i] - mn1);
            float rs0 = 0.f, rs1 = 0.f;
#pragma unroll
            for (int j = 0; j < 4; ++j) {
                float p0 = __expf(s0[i][j] - mn0);
                float p1 = __expf(s1t[i][j] - mn1);
                sP0[(ty * 4 + i) * KPAD + tx * 4 + j] = p0;
                sP1[(ty * 4 + i) * KPAD + tx * 4 + j] = p1;
                rs0 += p0; rs1 += p1;
            }
#pragma unroll
            for (int o = 8; o; o >>= 1) {
                rs0 += __shfl_xor_sync(0xffffffffu, rs0, o);
                rs1 += __shfl_xor_sync(0xffffffffu, rs1, o);
            }
            l0[i] = l0[i] * al0 + rs0; m0[i] = mn0;
            l1[i] = l1[i] * al1 + rs1; m1[i] = mn1;
            mul4(a0[i][0], al0); mul4(a0[i][1], al0);
            mul4(a1[i][0], al1); mul4(a1[i][1], al1);
        }
        __syncthreads();  // sP visible to all before PV

        // acc += P @ V (both half-heads share V)
#pragma unroll
        for (int c4 = 0; c4 < 16; ++c4) {
            float4 va[4][2];
#pragma unroll
            for (int cc = 0; cc < 4; ++cc) {
                va[cc][0] = *(const float4*)&sV[(c4 * 4 + cc) * VPAD + tx * 8];
                va[cc][1] = *(const float4*)&sV[(c4 * 4 + cc) * VPAD + tx * 8 + 4];
            }
#pragma unroll
            for (int i = 0; i < 4; ++i) {
                float4 p0 = *(const float4*)&sP0[(ty * 4 + i) * KPAD + c4 * 4];
                float4 p1 = *(const float4*)&sP1[(ty * 4 + i) * KPAD + c4 * 4];
                float pv0[4] = {p0.x, p0.y, p0.z, p0.w};
                float pv1[4] = {p1.x, p1.y, p1.z, p1.w};
#pragma unroll
                for (int cc = 0; cc < 4; ++cc) {
                    fma4(a0[i][0], pv0[cc], va[cc][0]);
                    fma4(a0[i][1], pv0[cc], va[cc][1]);
                    fma4(a1[i][0], pv1[cc], va[cc][0]);
                    fma4(a1[i][1], pv1[cc], va[cc][1]);
                }
            }
        }
    }

    // Epilogue: o = acc0/l0 - lam*acc1/l1, then per-head LayerNorm over 128.
    float4 gv0 = *(const float4*)&lng[tx * 8];
    float4 gv1 = *(const float4*)&lng[tx * 8 + 4];
    float4 bv0 = *(const float4*)&lnb[tx * 8];
    float4 bv1 = *(const float4*)&lnb[tx * 8 + 4];
#pragma unroll
    for (int i = 0; i < 4; ++i) {
        float il0 = 1.f / l0[i];
        float il1 = lam / l1[i];
        float o8[8];
        o8[0] = a0[i][0].x * il0 - a1[i][0].x * il1;
        o8[1] = a0[i][0].y * il0 - a1[i][0].y * il1;
        o8[2] = a0[i][0].z * il0 - a1[i][0].z * il1;
        o8[3] = a0[i][0].w * il0 - a1[i][0].w * il1;
        o8[4] = a0[i][1].x * il0 - a1[i][1].x * il1;
        o8[5] = a0[i][1].y * il0 - a1[i][1].y * il1;
        o8[6] = a0[i][1].z * il0 - a1[i][1].z * il1;
        o8[7] = a0[i][1].w * il0 - a1[i][1].w * il1;
        float s = 0.f, s2 = 0.f;
#pragma unroll
        for (int jj = 0; jj < 8; ++jj) { s += o8[jj]; s2 += o8[jj] * o8[jj]; }
#pragma unroll
        for (int o = 8; o; o >>= 1) {
            s += __shfl_xor_sync(0xffffffffu, s, o);
            s2 += __shfl_xor_sync(0xffffffffu, s2, o);
        }
        float mu = s * (1.f / 128.f);
        float var = s2 * (1.f / 128.f) - mu * mu;
        float rstd = rsqrtf(var + 1e-5f);
        float g8[8] = {gv0.x, gv0.y, gv0.z, gv0.w, gv1.x, gv1.y, gv1.z, gv1.w};
        float b8[8] = {bv0.x, bv0.y, bv0.z, bv0.w, bv1.x, bv1.y, bv1.z, bv1.w};
        float y[8];
#pragma unroll
        for (int jj = 0; jj < 8; ++jj) y[jj] = (o8[jj] - mu) * rstd * g8[jj] + b8[jj];
        float* dst = out + ((size_t)(b * NN + qbase + ty * 4 + i)) * EE + h * DV + tx * 8;
        *(float4*)dst = make_float4(y[0], y[1], y[2], y[3]);
        *(float4*)(dst + 4) = make_float4(y[4], y[5], y[6], y[7]);
    }
}

// ---------------------------------------------------------------------------
extern "C" void kernel_launch(void* const* d_in, const int* in_sizes, int n_in,
                              void* d_out, int out_size) {
    const float* x   = (const float*)d_in[0];
    const float* Wq  = (const float*)d_in[1];
    const float* Wk  = (const float*)d_in[2];
    const float* Wv  = (const float*)d_in[3];
    const float* Wo  = (const float*)d_in[4];
    const float* lq1 = (const float*)d_in[5];
    const float* lk1 = (const float*)d_in[6];
    const float* lq2 = (const float*)d_in[7];
    const float* lk2 = (const float*)d_in[8];
    const float* lng = (const float*)d_in[9];
    const float* lnb = (const float*)d_in[10];
    float* out = (float*)d_out;

    float *qp, *kp, *vp, *ap;
    cudaGetSymbolAddress((void**)&qp, g_q);
    cudaGetSymbolAddress((void**)&kp, g_k);
    cudaGetSymbolAddress((void**)&vp, g_v);
    cudaGetSymbolAddress((void**)&ap, g_att);

    const int M = BB * NN;  // 4096
    dim3 gg(EE / 128, M / 128);  // (8, 32)

    sgemm_kernel<<<gg, 256>>>(x, Wq, qp, M, EE, EE, 0.125f);  // q * D^-0.5
    sgemm_kernel<<<gg, 256>>>(x, Wk, kp, M, EE, EE, 1.f);
    sgemm_kernel<<<gg, 256>>>(x, Wv, vp, M, EE, EE, 1.f);
    lambda_kernel<<<1, 32>>>(lq1, lk1, lq2, lk2);

    int smem = (32 * 64 * 2 + 64 * KPAD * 2 + 64 * VPAD + 32 * KPAD * 2) * 4;  // 102400 B
    cudaFuncSetAttribute(flash_kernel, cudaFuncAttributeMaxDynamicSharedMemorySize, smem);
    dim3 fg(NN / 32, HH, BB);  // (64, 8, 2)
    flash_kernel<<<fg, 128, smem>>>(qp, kp, vp, lng, lnb, ap);

    sgemm_kernel<<<gg, 256>>>(ap, Wo, out, M, EE, EE, 1.f);
}

// round 3
// speedup vs baseline: 3.1596x; 3.1529x over previous
#include <cuda_runtime.h>
#include <cuda_bf16.h>
#include <math.h>
#include <stdint.h>

#define BB 2
#define NN 2048
#define EE 1024
#define HH 8
#define DD 64
#define MM (BB*NN)

typedef __nv_bfloat16 bf16;
typedef __nv_bfloat162 bf162;

// ---------------- scratch (__device__ globals; no runtime alloc) ----------------
__device__ bf16 g_wbh[4u * EE * EE];
__device__ bf16 g_wbl[4u * EE * EE];
__device__ bf16 g_xh[MM * EE], g_xl[MM * EE];
__device__ bf16 g_qh[MM * EE], g_ql[MM * EE];
__device__ bf16 g_kh[MM * EE], g_kl[MM * EE];
__device__ bf16 g_vh[MM * EE], g_vl[MM * EE];
__device__ bf16 g_ah[MM * EE], g_al[MM * EE];
__device__ float g_lambda;

// ---------------- helpers ----------------
__device__ __forceinline__ uint32_t s2u(const void* p) {
    return (uint32_t)__cvta_generic_to_shared(p);
}
__device__ __forceinline__ void ldsm4(uint32_t* r, uint32_t a) {
    asm volatile("ldmatrix.sync.aligned.m8n8.x4.shared.b16 {%0,%1,%2,%3},[%4];\n"
                 : "=r"(r[0]), "=r"(r[1]), "=r"(r[2]), "=r"(r[3]) : "r"(a));
}
__device__ __forceinline__ void ldsm4t(uint32_t* r, uint32_t a) {
    asm volatile("ldmatrix.sync.aligned.m8n8.x4.trans.shared.b16 {%0,%1,%2,%3},[%4];\n"
                 : "=r"(r[0]), "=r"(r[1]), "=r"(r[2]), "=r"(r[3]) : "r"(a));
}
__device__ __forceinline__ void mma16816(float* d, const uint32_t* a, uint32_t b0, uint32_t b1) {
    asm volatile("mma.sync.aligned.m16n8k16.row.col.f32.bf16.bf16.f32 "
                 "{%0,%1,%2,%3},{%4,%5,%6,%7},{%8,%9},{%0,%1,%2,%3};\n"
                 : "+f"(d[0]), "+f"(d[1]), "+f"(d[2]), "+f"(d[3])
                 : "r"(a[0]), "r"(a[1]), "r"(a[2]), "r"(a[3]), "r"(b0), "r"(b1));
}
// split two floats into packed bf16 hi-pair and lo-pair
__device__ __forceinline__ void split2(float a, float b, uint32_t& hi, uint32_t& lo) {
    bf162 h, l;
    h.x = __float2bfloat16(a); h.y = __float2bfloat16(b);
    l.x = __float2bfloat16(a - __bfloat162float(h.x));
    l.y = __float2bfloat16(b - __bfloat162float(h.y));
    hi = *(uint32_t*)&h; lo = *(uint32_t*)&l;
}

// ---------------- lambda ----------------
__global__ void lambda_kernel(const float* __restrict__ lq1, const float* __restrict__ lk1,
                              const float* __restrict__ lq2, const float* __restrict__ lk2) {
    int t = threadIdx.x;
    float s1 = 0.f, s2 = 0.f;
    for (int i = t; i < DD; i += 32) { s1 += lq1[i] * lk1[i]; s2 += lq2[i] * lk2[i]; }
#pragma unroll
    for (int o = 16; o; o >>= 1) {
        s1 += __shfl_xor_sync(0xffffffffu, s1, o);
        s2 += __shfl_xor_sync(0xffffffffu, s2, o);
    }
    if (t == 0) {
        double lam_init = 0.8 - 0.6 * exp(-0.3 * 12.0);
        g_lambda = expf(s1) - expf(s2) + (float)lam_init;
    }
}

// ---------------- split weights (no transpose; B loaded via ldmatrix.trans) ----------------
__global__ void wsplit_kernel(const float* __restrict__ W0, const float* __restrict__ W1,
                              const float* __restrict__ W2, const float* __restrict__ W3) {
    const float* W = (blockIdx.y == 0) ? W0 : (blockIdx.y == 1) ? W1 : (blockIdx.y == 2) ? W2 : W3;
    size_t base = (size_t)blockIdx.y * EE * EE;
    size_t i = (size_t)blockIdx.x * 1024 + threadIdx.x * 4;
    float4 v = *(const float4*)&W[i];
    bf16 h0 = __float2bfloat16(v.x), h1 = __float2bfloat16(v.y);
    bf16 h2 = __float2bfloat16(v.z), h3 = __float2bfloat16(v.w);
    bf162* oh = (bf162*)&g_wbh[base + i];
    bf162* ol = (bf162*)&g_wbl[base + i];
    bf162 a, b, c, d;
    a.x = h0; a.y = h1; b.x = h2; b.y = h3;
    c.x = __float2bfloat16(v.x - __bfloat162float(h0));
    c.y = __float2bfloat16(v.y - __bfloat162float(h1));
    d.x = __float2bfloat16(v.z - __bfloat162float(h2));
    d.y = __float2bfloat16(v.w - __bfloat162float(h3));
    oh[0] = a; oh[1] = b; ol[0] = c; ol[1] = d;
}

__global__ void xsplit_kernel(const float* __restrict__ x) {
    size_t i = (size_t)blockIdx.x * 1024 + threadIdx.x * 4;
    float4 v = *(const float4*)&x[i];
    bf16 h0 = __float2bfloat16(v.x), h1 = __float2bfloat16(v.y);
    bf16 h2 = __float2bfloat16(v.z), h3 = __float2bfloat16(v.w);
    bf162* oh = (bf162*)&g_xh[i];
    bf162* ol = (bf162*)&g_xl[i];
    bf162 a, b, c, d;
    a.x = h0; a.y = h1; b.x = h2; b.y = h3;
    c.x = __float2bfloat16(v.x - __bfloat162float(h0));
    c.y = __float2bfloat16(v.y - __bfloat162float(h1));
    d.x = __float2bfloat16(v.z - __bfloat162float(h2));
    d.y = __float2bfloat16(v.w - __bfloat162float(h3));
    oh[0] = a; oh[1] = b; ol[0] = c; ol[1] = d;
}

// ---------------- bf16-split MMA GEMM: C[4096,1024] = A[4096,1024] @ W[1024,1024] ----------------
// mode 0: write fp32 to Cf. mode 1: write split bf16 (alpha applied) to Ch/Cl.
__global__ __launch_bounds__(256) void mma_gemm(const bf16* __restrict__ Ah, const bf16* __restrict__ Al,
                                                const bf16* __restrict__ Wh, const bf16* __restrict__ Wl,
                                                float* __restrict__ Cf, bf16* __restrict__ Ch,
                                                bf16* __restrict__ Cl, float alpha, int mode) {
    __shared__ bf16 sAh[128 * 40], sAl[128 * 40];
    __shared__ bf16 sBh[32 * 136], sBl[32 * 136];
    const int tid = threadIdx.x, lane = tid & 31, wid = tid >> 5;
    const int wm = (wid >> 2) * 64, wn = (wid & 3) * 32;
    const int m0 = blockIdx.y * 128, n0 = blockIdx.x * 128;

    float acc[4][4][4];
#pragma unroll
    for (int i = 0; i < 4; ++i)
#pragma unroll
        for (int j = 0; j < 4; ++j)
#pragma unroll
            for (int q = 0; q < 4; ++q) acc[i][j][q] = 0.f;

    for (int kt = 0; kt < EE; kt += 32) {
        __syncthreads();
#pragma unroll
        for (int j = 0; j < 2; ++j) {
            int ch = tid + j * 256;
            int r = ch >> 2, s = (ch & 3) * 8;
            *(uint4*)&sAh[r * 40 + s] = *(const uint4*)&Ah[(size_t)(m0 + r) * EE + kt + s];
            *(uint4*)&sAl[r * 40 + s] = *(const uint4*)&Al[(size_t)(m0 + r) * EE + kt + s];
        }
#pragma unroll
        for (int j = 0; j < 2; ++j) {
            int ch = tid + j * 256;
            int r = ch >> 4, s = (ch & 15) * 8;
            *(uint4*)&sBh[r * 136 + s] = *(const uint4*)&Wh[(size_t)(kt + r) * EE + n0 + s];
            *(uint4*)&sBl[r * 136 + s] = *(const uint4*)&Wl[(size_t)(kt + r) * EE + n0 + s];
        }
        __syncthreads();
#pragma unroll
        for (int kg = 0; kg < 2; ++kg) {
            uint32_t ah[4][4], al[4][4], bh[4][2], bl[4][2];
#pragma unroll
            for (int i = 0; i < 4; ++i) {
                int off = (wm + i * 16 + (lane & 15)) * 40 + kg * 16 + (lane >> 4) * 8;
                ldsm4(ah[i], s2u(&sAh[off]));
                ldsm4(al[i], s2u(&sAl[off]));
            }
#pragma unroll
            for (int p = 0; p < 2; ++p) {
                int off = (kg * 16 + (lane & 15)) * 136 + wn + p * 16 + (lane >> 4) * 8;
                uint32_t t[4], u[4];
                ldsm4t(t, s2u(&sBh[off]));
                ldsm4t(u, s2u(&sBl[off]));
                bh[2 * p][0] = t[0]; bh[2 * p][1] = t[1];
                bh[2 * p + 1][0] = t[2]; bh[2 * p + 1][1] = t[3];
                bl[2 * p][0] = u[0]; bl[2 * p][1] = u[1];
                bl[2 * p + 1][0] = u[2]; bl[2 * p + 1][1] = u[3];
            }
#pragma unroll
            for (int i = 0; i < 4; ++i)
#pragma unroll
                for (int ni = 0; ni < 4; ++ni) {
                    mma16816(acc[i][ni], ah[i], bh[ni][0], bh[ni][1]);
                    mma16816(acc[i][ni], ah[i], bl[ni][0], bl[ni][1]);
                    mma16816(acc[i][ni], al[i], bh[ni][0], bh[ni][1]);
                }
        }
    }

#pragma unroll
    for (int mi = 0; mi < 4; ++mi) {
        int r0 = m0 + wm + mi * 16 + (lane >> 2);
        int r1 = r0 + 8;
#pragma unroll
        for (int ni = 0; ni < 4; ++ni) {
            int col = n0 + wn + ni * 8 + 2 * (lane & 3);
            if (mode == 0) {
                float2 a = make_float2(acc[mi][ni][0], acc[mi][ni][1]);
                float2 b = make_float2(acc[mi][ni][2], acc[mi][ni][3]);
                *(float2*)&Cf[(size_t)r0 * EE + col] = a;
                *(float2*)&Cf[(size_t)r1 * EE + col] = b;
            } else {
                uint32_t h, l;
                split2(acc[mi][ni][0] * alpha, acc[mi][ni][1] * alpha, h, l);
                *(uint32_t*)&Ch[(size_t)r0 * EE + col] = h;
                *(uint32_t*)&Cl[(size_t)r0 * EE + col] = l;
                split2(acc[mi][ni][2] * alpha, acc[mi][ni][3] * alpha, h, l);
                *(uint32_t*)&Ch[(size_t)r1 * EE + col] = h;
                *(uint32_t*)&Cl[(size_t)r1 * EE + col] = l;
            }
        }
    }
}

// ---------------- differential flash attention + fused LayerNorm (tensor cores) ----------------
// CTA: (qtile of 64 rows, head-pair hp, batch b). 4 warps x 16 q-rows.
// K tile: 32 keys. smem bf16 offsets (elements):
#define SQH 0
#define SQL 8704
#define SKH 17408
#define SKL 21760
#define SVH 26112
#define SVL 30464
#define FSM_BYTES ((30464 + 4352) * 2)

__global__ __launch_bounds__(128) void flash_kernel(const bf16* __restrict__ qh_, const bf16* __restrict__ ql_,
                                                    const bf16* __restrict__ kh_, const bf16* __restrict__ kl_,
                                                    const bf16* __restrict__ vh_, const bf16* __restrict__ vl_,
                                                    const float* __restrict__ lng, const float* __restrict__ lnb,
                                                    bf16* __restrict__ oh_, bf16* __restrict__ ol_) {
    extern __shared__ bf16 sm[];
    const int tid = threadIdx.x, lane = tid & 31, wid = tid >> 5;
    const int b = blockIdx.z, hp = blockIdx.y;
    const int q0 = blockIdx.x * 64;
    const int wrow = wid * 16;
    const float lam = g_lambda;

    // Load Q tile: 64 rows x 128 cols (both half-heads), hi+lo
#pragma unroll
    for (int j = 0; j < 8; ++j) {
        int ch = tid + j * 128;
        int r = ch >> 4, s = (ch & 15) * 8;
        size_t src = (size_t)(b * NN + q0 + r) * EE + hp * 128 + s;
        *(uint4*)&sm[SQH + r * 136 + s] = *(const uint4*)&qh_[src];
        *(uint4*)&sm[SQL + r * 136 + s] = *(const uint4*)&ql_[src];
    }

    float acc0[16][4], acc1[16][4];
#pragma unroll
    for (int i = 0; i < 16; ++i)
#pragma unroll
        for (int j = 0; j < 4; ++j) { acc0[i][j] = 0.f; acc1[i][j] = 0.f; }
    float mA[2], mB[2], lA[2], lB[2];
    mA[0] = mA[1] = mB[0] = mB[1] = -1e30f;
    lA[0] = lA[1] = lB[0] = lB[1] = 0.f;

    for (int kt = 0; kt < NN; kt += 32) {
        __syncthreads();
#pragma unroll
        for (int j = 0; j < 4; ++j) {
            int ch = tid + j * 128;
            int r = ch >> 4, s = (ch & 15) * 8;
            size_t src = (size_t)(b * NN + kt + r) * EE + hp * 128 + s;
            *(uint4*)&sm[SKH + r * 136 + s] = *(const uint4*)&kh_[src];
            *(uint4*)&sm[SKL + r * 136 + s] = *(const uint4*)&kl_[src];
            *(uint4*)&sm[SVH + r * 136 + s] = *(const uint4*)&vh_[src];
            *(uint4*)&sm[SVL + r * 136 + s] = *(const uint4*)&vl_[src];
        }
        __syncthreads();

#pragma unroll
        for (int half = 0; half < 2; ++half) {
            float (*ac)[4] = half ? acc1 : acc0;
            float S[4][4];
#pragma unroll
            for (int i = 0; i < 4; ++i)
#pragma unroll
                for (int j = 0; j < 4; ++j) S[i][j] = 0.f;

            // S = Qh*Kh + Qh*Kl + Ql*Kh over d = half*64 .. +64
#pragma unroll
            for (int kg = 0; kg < 4; ++kg) {
                int d0 = half * 64 + kg * 16 + (lane >> 4) * 8;
                uint32_t qh[4], ql[4];
                ldsm4(qh, s2u(&sm[SQH + (wrow + (lane & 15)) * 136 + d0]));
                ldsm4(ql, s2u(&sm[SQL + (wrow + (lane & 15)) * 136 + d0]));
#pragma unroll
                for (int p = 0; p < 2; ++p) {
                    uint32_t t[4], u[4];
                    int off = (p * 16 + (lane & 15)) * 136 + d0;
                    ldsm4(t, s2u(&sm[SKH + off]));
                    ldsm4(u, s2u(&sm[SKL + off]));
                    mma16816(S[2 * p], qh, t[0], t[2]);
                    mma16816(S[2 * p], qh, u[0], u[2]);
                    mma16816(S[2 * p], ql, t[0], t[2]);
                    mma16816(S[2 * p + 1], qh, t[1], t[3]);
                    mma16816(S[2 * p + 1], qh, u[1], u[3]);
                    mma16816(S[2 * p + 1], ql, t[1], t[3]);
                }
            }

            // online softmax over 32 keys (rows: A = lane/4, B = lane/4+8)
            float mxA = -1e30f, mxB = -1e30f;
#pragma unroll
            for (int ng = 0; ng < 4; ++ng) {
                mxA = fmaxf(mxA, fmaxf(S[ng][0], S[ng][1]));
                mxB = fmaxf(mxB, fmaxf(S[ng][2], S[ng][3]));
            }
            mxA = fmaxf(mxA, __shfl_xor_sync(0xffffffffu, mxA, 1));
            mxA = fmaxf(mxA, __shfl_xor_sync(0xffffffffu, mxA, 2));
            mxB = fmaxf(mxB, __shfl_xor_sync(0xffffffffu, mxB, 1));
            mxB = fmaxf(mxB, __shfl_xor_sync(0xffffffffu, mxB, 2));
            float nmA = fmaxf(mA[half], mxA), nmB = fmaxf(mB[half], mxB);
            float aA = __expf(mA[half] - nmA), aB = __expf(mB[half] - nmB);
            float sA = 0.f, sB = 0.f;
#pragma unroll
            for (int ng = 0; ng < 4; ++ng) {
                S[ng][0] = __expf(S[ng][0] - nmA);
                S[ng][1] = __expf(S[ng][1] - nmA);
                S[ng][2] = __expf(S[ng][2] - nmB);
                S[ng][3] = __expf(S[ng][3] - nmB);
                sA += S[ng][0] + S[ng][1];
                sB += S[ng][2] + S[ng][3];
            }
            sA += __shfl_xor_sync(0xffffffffu, sA, 1);
            sA += __shfl_xor_sync(0xffffffffu, sA, 2);
            sB += __shfl_xor_sync(0xffffffffu, sB, 1);
            sB += __shfl_xor_sync(0xffffffffu, sB, 2);
            lA[half] = lA[half] * aA + sA; mA[half] = nmA;
            lB[half] = lB[half] * aB + sB; mB[half] = nmB;
#pragma unroll
            for (int ng = 0; ng < 16; ++ng) {
                ac[ng][0] *= aA; ac[ng][1] *= aA;
                ac[ng][2] *= aB; ac[ng][3] *= aB;
            }
            // P a-fragments (split) straight from S accumulator layout
            uint32_t ph[2][4], pl[2][4];
#pragma unroll
            for (int j = 0; j < 2; ++j) {
                split2(S[2 * j][0], S[2 * j][1], ph[j][0], pl[j][0]);
                split2(S[2 * j][2], S[2 * j][3], ph[j][1], pl[j][1]);
                split2(S[2 * j + 1][0], S[2 * j + 1][1], ph[j][2], pl[j][2]);
                split2(S[2 * j + 1][2], S[2 * j + 1][3], ph[j][3], pl[j][3]);
            }
            // acc += P @ V (V shared across halves)
#pragma unroll
            for (int kg2 = 0; kg2 < 2; ++kg2) {
#pragma unroll
                for (int np = 0; np < 8; ++np) {
                    uint32_t vh[4], vl[4];
                    int off = (kg2 * 16 + (lane & 15)) * 136 + np * 16 + (lane >> 4) * 8;
                    ldsm4t(vh, s2u(&sm[SVH + off]));
                    ldsm4t(vl, s2u(&sm[SVL + off]));
                    mma16816(ac[2 * np], ph[kg2], vh[0], vh[1]);
                    mma16816(ac[2 * np], ph[kg2], vl[0], vl[1]);
                    mma16816(ac[2 * np], pl[kg2], vh[0], vh[1]);
                    mma16816(ac[2 * np + 1], ph[kg2], vh[2], vh[3]);
                    mma16816(ac[2 * np + 1], ph[kg2], vl[2], vl[3]);
                    mma16816(ac[2 * np + 1], pl[kg2], vh[2], vh[3]);
                }
            }
        }
    }

    // Epilogue: o = acc0/l0 - lam*acc1/l1, per-head LayerNorm over 128 channels.
    float i0A = 1.f / lA[0], i0B = 1.f / lB[0];
    float i1A = lam / lA[1], i1B = lam / lB[1];
    float suA = 0.f, sqA = 0.f, suB = 0.f, sqB = 0.f;
#pragma unroll
    for (int ng = 0; ng < 16; ++ng) {
        float o0 = acc0[ng][0] * i0A - acc1[ng][0] * i1A;
        float o1 = acc0[ng][1] * i0A - acc1[ng][1] * i1A;
        float o2 = acc0[ng][2] * i0B - acc1[ng][2] * i1B;
        float o3 = acc0[ng][3] * i0B - acc1[ng][3] * i1B;
        acc0[ng][0] = o0; acc0[ng][1] = o1; acc0[ng][2] = o2; acc0[ng][3] = o3;
        suA += o0 + o1; sqA += o0 * o0 + o1 * o1;
        suB += o2 + o3; sqB += o2 * o2 + o3 * o3;
    }
    suA += __shfl_xor_sync(0xffffffffu, suA, 1); suA += __shfl_xor_sync(0xffffffffu, suA, 2);
    sqA += __shfl_xor_sync(0xffffffffu, sqA, 1); sqA += __shfl_xor_sync(0xffffffffu, sqA, 2);
    suB += __shfl_xor_sync(0xffffffffu, suB, 1); suB += __shfl_xor_sync(0xffffffffu, suB, 2);
    sqB += __shfl_xor_sync(0xffffffffu, sqB, 1); sqB += __shfl_xor_sync(0xffffffffu, sqB, 2);
    float muA = suA * (1.f / 128.f), muB = suB * (1.f / 128.f);
    float rsA = rsqrtf(sqA * (1.f / 128.f) - muA * muA + 1e-5f);
    float rsB = rsqrtf(sqB * (1.f / 128.f) - muB * muB + 1e-5f);

    int rA = b * NN + q0 + wrow + (lane >> 2);
    int rB = rA + 8;
#pragma unroll
    for (int ng = 0; ng < 16; ++ng) {
        int col = ng * 8 + 2 * (lane & 3);
        float g0 = lng[col], g1 = lng[col + 1];
        float b0 = lnb[col], b1 = lnb[col + 1];
        float y0 = (acc0[ng][0] - muA) * rsA * g0 + b0;
        float y1 = (acc0[ng][1] - muA) * rsA * g1 + b1;
        float y2 = (acc0[ng][2] - muB) * rsB * g0 + b0;
        float y3 = (acc0[ng][3] - muB) * rsB * g1 + b1;
        uint32_t h, l;
        size_t dA = (size_t)rA * EE + hp * 128 + col;
        size_t dB = (size_t)rB * EE + hp * 128 + col;
        split2(y0, y1, h, l);
        *(uint32_t*)&oh_[dA] = h; *(uint32_t*)&ol_[dA] = l;
        split2(y2, y3, h, l);
        *(uint32_t*)&oh_[dB] = h; *(uint32_t*)&ol_[dB] = l;
    }
}

// ---------------------------------------------------------------------------
extern "C" void kernel_launch(void* const* d_in, const int* in_sizes, int n_in,
                              void* d_out, int out_size) {
    const float* x   = (const float*)d_in[0];
    const float* Wq  = (const float*)d_in[1];
    const float* Wk  = (const float*)d_in[2];
    const float* Wv  = (const float*)d_in[3];
    const float* Wo  = (const float*)d_in[4];
    const float* lq1 = (const float*)d_in[5];
    const float* lk1 = (const float*)d_in[6];
    const float* lq2 = (const float*)d_in[7];
    const float* lk2 = (const float*)d_in[8];
    const float* lng = (const float*)d_in[9];
    const float* lnb = (const float*)d_in[10];
    float* out = (float*)d_out;

    bf16 *wbh, *wbl, *xh, *xl, *qh, *ql, *kh, *kl, *vh, *vl, *ah, *al;
    cudaGetSymbolAddress((void**)&wbh, g_wbh);
    cudaGetSymbolAddress((void**)&wbl, g_wbl);
    cudaGetSymbolAddress((void**)&xh, g_xh);
    cudaGetSymbolAddress((void**)&xl, g_xl);
    cudaGetSymbolAddress((void**)&qh, g_qh);
    cudaGetSymbolAddress((void**)&ql, g_ql);
    cudaGetSymbolAddress((void**)&kh, g_kh);
    cudaGetSymbolAddress((void**)&kl, g_kl);
    cudaGetSymbolAddress((void**)&vh, g_vh);
    cudaGetSymbolAddress((void**)&vl, g_vl);
    cudaGetSymbolAddress((void**)&ah, g_ah);
    cudaGetSymbolAddress((void**)&al, g_al);

    wsplit_kernel<<<dim3(1024, 4), 256>>>(Wq, Wk, Wv, Wo);
    xsplit_kernel<<<4096, 256>>>(x);
    lambda_kernel<<<1, 32>>>(lq1, lk1, lq2, lk2);

    const size_t WSZ = (size_t)EE * EE;
    dim3 gg(8, 32);
    mma_gemm<<<gg, 256>>>(xh, xl, wbh + 0 * WSZ, wbl + 0 * WSZ, nullptr, qh, ql, 0.125f, 1);
    mma_gemm<<<gg, 256>>>(xh, xl, wbh + 1 * WSZ, wbl + 1 * WSZ, nullptr, kh, kl, 1.f, 1);
    mma_gemm<<<gg, 256>>>(xh, xl, wbh + 2 * WSZ, wbl + 2 * WSZ, nullptr, vh, vl, 1.f, 1);

    cudaFuncSetAttribute(flash_kernel, cudaFuncAttributeMaxDynamicSharedMemorySize, FSM_BYTES);
    dim3 fg(NN / 64, HH, BB);  // (32, 8, 2)
    flash_kernel<<<fg, 128, FSM_BYTES>>>(qh, ql, kh, kl, vh, vl, lng, lnb, ah, al);

    mma_gemm<<<gg, 256>>>(ah, al, wbh + 3 * WSZ, wbl + 3 * WSZ, out, nullptr, nullptr, 1.f, 0);
}

// round 4
// speedup vs baseline: 3.8492x; 1.2183x over previous
#include <cuda_runtime.h>
#include <cuda_bf16.h>
#include <math.h>
#include <stdint.h>

#define BB 2
#define NN 2048
#define EE 1024
#define HH 8
#define DD 64
#define MM (BB*NN)

typedef __nv_bfloat16 bf16;
typedef __nv_bfloat162 bf162;

// ---------------- scratch (__device__ globals; no runtime alloc) ----------------
__device__ bf16 g_wbh[4u * EE * EE];
__device__ bf16 g_wbl[4u * EE * EE];
__device__ bf16 g_xh[MM * EE], g_xl[MM * EE];
__device__ bf16 g_qh[MM * EE], g_ql[MM * EE];
__device__ bf16 g_kh[MM * EE], g_kl[MM * EE];
__device__ bf16 g_vh[MM * EE], g_vl[MM * EE];
__device__ bf16 g_ah[MM * EE], g_al[MM * EE];
__device__ float g_lambda;

// ---------------- helpers ----------------
__device__ __forceinline__ uint32_t s2u(const void* p) {
    return (uint32_t)__cvta_generic_to_shared(p);
}
__device__ __forceinline__ void ldsm4(uint32_t* r, uint32_t a) {
    asm volatile("ldmatrix.sync.aligned.m8n8.x4.shared.b16 {%0,%1,%2,%3},[%4];\n"
                 : "=r"(r[0]), "=r"(r[1]), "=r"(r[2]), "=r"(r[3]) : "r"(a));
}
__device__ __forceinline__ void ldsm4t(uint32_t* r, uint32_t a) {
    asm volatile("ldmatrix.sync.aligned.m8n8.x4.trans.shared.b16 {%0,%1,%2,%3},[%4];\n"
                 : "=r"(r[0]), "=r"(r[1]), "=r"(r[2]), "=r"(r[3]) : "r"(a));
}
__device__ __forceinline__ void mma16816(float* d, const uint32_t* a, uint32_t b0, uint32_t b1) {
    asm volatile("mma.sync.aligned.m16n8k16.row.col.f32.bf16.bf16.f32 "
                 "{%0,%1,%2,%3},{%4,%5,%6,%7},{%8,%9},{%0,%1,%2,%3};\n"
                 : "+f"(d[0]), "+f"(d[1]), "+f"(d[2]), "+f"(d[3])
                 : "r"(a[0]), "r"(a[1]), "r"(a[2]), "r"(a[3]), "r"(b0), "r"(b1));
}
__device__ __forceinline__ void cpa16(uint32_t dst, const void* src) {
    asm volatile("cp.async.cg.shared.global [%0], [%1], 16;\n" :: "r"(dst), "l"(src));
}
#define CP_COMMIT asm volatile("cp.async.commit_group;\n")
#define CP_WAIT1  asm volatile("cp.async.wait_group 1;\n")
__device__ __forceinline__ float ex2(float x) {
    float y; asm("ex2.approx.f32 %0,%1;\n" : "=f"(y) : "f"(x)); return y;
}
__device__ __forceinline__ void split2(float a, float b, uint32_t& hi, uint32_t& lo) {
    bf162 h, l;
    h.x = __float2bfloat16(a); h.y = __float2bfloat16(b);
    l.x = __float2bfloat16(a - __bfloat162float(h.x));
    l.y = __float2bfloat16(b - __bfloat162float(h.y));
    hi = *(uint32_t*)&h; lo = *(uint32_t*)&l;
}

// ---------------- lambda ----------------
__global__ void lambda_kernel(const float* __restrict__ lq1, const float* __restrict__ lk1,
                              const float* __restrict__ lq2, const float* __restrict__ lk2) {
    int t = threadIdx.x;
    float s1 = 0.f, s2 = 0.f;
    for (int i = t; i < DD; i += 32) { s1 += lq1[i] * lk1[i]; s2 += lq2[i] * lk2[i]; }
#pragma unroll
    for (int o = 16; o; o >>= 1) {
        s1 += __shfl_xor_sync(0xffffffffu, s1, o);
        s2 += __shfl_xor_sync(0xffffffffu, s2, o);
    }
    if (t == 0) {
        double lam_init = 0.8 - 0.6 * exp(-0.3 * 12.0);
        g_lambda = expf(s1) - expf(s2) + (float)lam_init;
    }
}

// ---------------- split kernels ----------------
__global__ void wsplit_kernel(const float* __restrict__ W0, const float* __restrict__ W1,
                              const float* __restrict__ W2, const float* __restrict__ W3) {
    const float* W = (blockIdx.y == 0) ? W0 : (blockIdx.y == 1) ? W1 : (blockIdx.y == 2) ? W2 : W3;
    size_t base = (size_t)blockIdx.y * EE * EE;
    size_t i = (size_t)blockIdx.x * 1024 + threadIdx.x * 4;
    float4 v = *(const float4*)&W[i];
    bf16 h0 = __float2bfloat16(v.x), h1 = __float2bfloat16(v.y);
    bf16 h2 = __float2bfloat16(v.z), h3 = __float2bfloat16(v.w);
    bf162* oh = (bf162*)&g_wbh[base + i];
    bf162* ol = (bf162*)&g_wbl[base + i];
    bf162 a, b, c, d;
    a.x = h0; a.y = h1; b.x = h2; b.y = h3;
    c.x = __float2bfloat16(v.x - __bfloat162float(h0));
    c.y = __float2bfloat16(v.y - __bfloat162float(h1));
    d.x = __float2bfloat16(v.z - __bfloat162float(h2));
    d.y = __float2bfloat16(v.w - __bfloat162float(h3));
    oh[0] = a; oh[1] = b; ol[0] = c; ol[1] = d;
}

__global__ void xsplit_kernel(const float* __restrict__ x) {
    size_t i = (size_t)blockIdx.x * 1024 + threadIdx.x * 4;
    float4 v = *(const float4*)&x[i];
    bf16 h0 = __float2bfloat16(v.x), h1 = __float2bfloat16(v.y);
    bf16 h2 = __float2bfloat16(v.z), h3 = __float2bfloat16(v.w);
    bf162* oh = (bf162*)&g_xh[i];
    bf162* ol = (bf162*)&g_xl[i];
    bf162 a, b, c, d;
    a.x = h0; a.y = h1; b.x = h2; b.y = h3;
    c.x = __float2bfloat16(v.x - __bfloat162float(h0));
    c.y = __float2bfloat16(v.y - __bfloat162float(h1));
    d.x = __float2bfloat16(v.z - __bfloat162float(h2));
    d.y = __float2bfloat16(v.w - __bfloat162float(h3));
    oh[0] = a; oh[1] = b; ol[0] = c; ol[1] = d;
}

// ---------------- bf16-split MMA GEMM, cp.async double-buffered ----------------
// smem layout (bf16 elements):
//   A buf b: AH at b*10240, AL at b*10240+5120   (128 rows x 32 cols, pitch 40)
//   B buf b: BH at 20480+b*8704, BL at +4352     (32 rows x 128 cols, pitch 136)
#define GSM_ELEMS 37888
#define GSM_BYTES (GSM_ELEMS * 2)

__global__ __launch_bounds__(256, 2) void mma_gemm(const bf16* __restrict__ Ah, const bf16* __restrict__ Al,
                                                   const bf16* __restrict__ Wh, const bf16* __restrict__ Wl,
                                                   float* __restrict__ Cf, bf16* __restrict__ Ch,
                                                   bf16* __restrict__ Cl, float alpha, int mode) {
    extern __shared__ bf16 sg[];
    const int tid = threadIdx.x, lane = tid & 31, wid = tid >> 5;
    const int wm = (wid >> 2) * 64, wn = (wid & 3) * 32;
    const int m0 = blockIdx.y * 128, n0 = blockIdx.x * 128;

    float acc[4][4][4];
#pragma unroll
    for (int i = 0; i < 4; ++i)
#pragma unroll
        for (int j = 0; j < 4; ++j)
#pragma unroll
            for (int q = 0; q < 4; ++q) acc[i][j][q] = 0.f;

    // copy tile at k-offset kt into buffer bu
    auto copy_tile = [&](int kt, int bu) {
        int ao = bu * 10240, bo = 20480 + bu * 8704;
#pragma unroll
        for (int j = 0; j < 2; ++j) {
            int ch = tid + j * 256;
            int r = ch >> 2, s = (ch & 3) * 8;
            cpa16(s2u(&sg[ao + r * 40 + s]), &Ah[(size_t)(m0 + r) * EE + kt + s]);
            cpa16(s2u(&sg[ao + 5120 + r * 40 + s]), &Al[(size_t)(m0 + r) * EE + kt + s]);
        }
#pragma unroll
        for (int j = 0; j < 2; ++j) {
            int ch = tid + j * 256;
            int r = ch >> 4, s = (ch & 15) * 8;
            cpa16(s2u(&sg[bo + r * 136 + s]), &Wh[(size_t)(kt + r) * EE + n0 + s]);
            cpa16(s2u(&sg[bo + 4352 + r * 136 + s]), &Wl[(size_t)(kt + r) * EE + n0 + s]);
        }
    };

    copy_tile(0, 0);
    CP_COMMIT;

    int bu = 0;
    for (int kt = 0; kt < EE; kt += 32, bu ^= 1) {
        if (kt + 32 < EE) copy_tile(kt + 32, bu ^ 1);
        CP_COMMIT;
        CP_WAIT1;
        __syncthreads();
        int ao = bu * 10240, bo = 20480 + bu * 8704;
#pragma unroll
        for (int kg = 0; kg < 2; ++kg) {
            uint32_t ah[4][4], al[4][4], bh[4][2], bl[4][2];
#pragma unroll
            for (int i = 0; i < 4; ++i) {
                int off = (wm + i * 16 + (lane & 15)) * 40 + kg * 16 + (lane >> 4) * 8;
                ldsm4(ah[i], s2u(&sg[ao + off]));
                ldsm4(al[i], s2u(&sg[ao + 5120 + off]));
            }
#pragma unroll
            for (int p = 0; p < 2; ++p) {
                int off = (kg * 16 + (lane & 15)) * 136 + wn + p * 16 + (lane >> 4) * 8;
                uint32_t t[4], u[4];
                ldsm4t(t, s2u(&sg[bo + off]));
                ldsm4t(u, s2u(&sg[bo + 4352 + off]));
                bh[2 * p][0] = t[0]; bh[2 * p][1] = t[1];
                bh[2 * p + 1][0] = t[2]; bh[2 * p + 1][1] = t[3];
                bl[2 * p][0] = u[0]; bl[2 * p][1] = u[1];
                bl[2 * p + 1][0] = u[2]; bl[2 * p + 1][1] = u[3];
            }
#pragma unroll
            for (int i = 0; i < 4; ++i)
#pragma unroll
                for (int ni = 0; ni < 4; ++ni) {
                    mma16816(acc[i][ni], ah[i], bh[ni][0], bh[ni][1]);
                    mma16816(acc[i][ni], ah[i], bl[ni][0], bl[ni][1]);
                    mma16816(acc[i][ni], al[i], bh[ni][0], bh[ni][1]);
                }
        }
        __syncthreads();
    }

#pragma unroll
    for (int mi = 0; mi < 4; ++mi) {
        int r0 = m0 + wm + mi * 16 + (lane >> 2);
        int r1 = r0 + 8;
#pragma unroll
        for (int ni = 0; ni < 4; ++ni) {
            int col = n0 + wn + ni * 8 + 2 * (lane & 3);
            if (mode == 0) {
                float2 a = make_float2(acc[mi][ni][0], acc[mi][ni][1]);
                float2 b = make_float2(acc[mi][ni][2], acc[mi][ni][3]);
                *(float2*)&Cf[(size_t)r0 * EE + col] = a;
                *(float2*)&Cf[(size_t)r1 * EE + col] = b;
            } else {
                uint32_t h, l;
                split2(acc[mi][ni][0] * alpha, acc[mi][ni][1] * alpha, h, l);
                *(uint32_t*)&Ch[(size_t)r0 * EE + col] = h;
                *(uint32_t*)&Cl[(size_t)r0 * EE + col] = l;
                split2(acc[mi][ni][2] * alpha, acc[mi][ni][3] * alpha, h, l);
                *(uint32_t*)&Ch[(size_t)r1 * EE + col] = h;
                *(uint32_t*)&Cl[(size_t)r1 * EE + col] = l;
            }
        }
    }
}

// ---------------- differential flash attention + fused LayerNorm ----------------
// CTA: (64 q-rows, head-pair hp, batch b); 4 warps x 16 rows; 32-key tiles,
// double-buffered K/V via cp.async; V fragments hoisted across the two halves.
// smem (bf16 elements): Q hi 0, Q lo 8704; KV buf b at 17408+b*17408:
//   KH +0, KL +4352, VH +8704, VL +13056 (each 32x136)
#define SQH 0
#define SQL 8704
#define KVB 17408
#define FSM_ELEMS (17408 + 2 * 17408)
#define FSM_BYTES (FSM_ELEMS * 2)

__global__ __launch_bounds__(128, 2) void flash_kernel(const bf16* __restrict__ qh_, const bf16* __restrict__ ql_,
                                                       const bf16* __restrict__ kh_, const bf16* __restrict__ kl_,
                                                       const bf16* __restrict__ vh_, const bf16* __restrict__ vl_,
                                                       const float* __restrict__ lng, const float* __restrict__ lnb,
                                                       bf16* __restrict__ oh_, bf16* __restrict__ ol_) {
    extern __shared__ bf16 sm[];
    const int tid = threadIdx.x, lane = tid & 31, wid = tid >> 5;
    const int b = blockIdx.z, hp = blockIdx.y;
    const int q0 = blockIdx.x * 64;
    const int wrow = wid * 16;
    const float lam = g_lambda;

    auto copy_kv = [&](int kt, int bu) {
        int base = KVB + bu * 17408;
#pragma unroll
        for (int j = 0; j < 4; ++j) {
            int ch = tid + j * 128;
            int r = ch >> 4, s = (ch & 15) * 8;
            size_t src = (size_t)(b * NN + kt + r) * EE + hp * 128 + s;
            cpa16(s2u(&sm[base + r * 136 + s]), &kh_[src]);
            cpa16(s2u(&sm[base + 4352 + r * 136 + s]), &kl_[src]);
            cpa16(s2u(&sm[base + 8704 + r * 136 + s]), &vh_[src]);
            cpa16(s2u(&sm[base + 13056 + r * 136 + s]), &vl_[src]);
        }
    };

    // Q tile (64 x 128, hi+lo) + first KV tile, one async group
#pragma unroll
    for (int j = 0; j < 8; ++j) {
        int ch = tid + j * 128;
        int r = ch >> 4, s = (ch & 15) * 8;
        size_t src = (size_t)(b * NN + q0 + r) * EE + hp * 128 + s;
        cpa16(s2u(&sm[SQH + r * 136 + s]), &qh_[src]);
        cpa16(s2u(&sm[SQL + r * 136 + s]), &ql_[src]);
    }
    copy_kv(0, 0);
    CP_COMMIT;

    float acc0[16][4], acc1[16][4];
#pragma unroll
    for (int i = 0; i < 16; ++i)
#pragma unroll
        for (int j = 0; j < 4; ++j) { acc0[i][j] = 0.f; acc1[i][j] = 0.f; }
    float mA[2], mB[2], lA[2], lB[2];
    mA[0] = mA[1] = mB[0] = mB[1] = -1e30f;
    lA[0] = lA[1] = lB[0] = lB[1] = 0.f;

    int bu = 0;
    for (int kt = 0; kt < NN; kt += 32, bu ^= 1) {
        if (kt + 32 < NN) copy_kv(kt + 32, bu ^ 1);
        CP_COMMIT;
        CP_WAIT1;
        __syncthreads();
        const int lb = KVB + bu * 17408;

        uint32_t ph[2][2][4], pl[2][2][4];
#pragma unroll
        for (int half = 0; half < 2; ++half) {
            float (*ac)[4] = half ? acc1 : acc0;
            float S[4][4];
#pragma unroll
            for (int i = 0; i < 4; ++i)
#pragma unroll
                for (int j = 0; j < 4; ++j) S[i][j] = 0.f;

            // S = Qh*Kh + Qh*Kl + Ql*Kh over d = half*64 .. +64 (log2e pre-folded)
#pragma unroll
            for (int kg = 0; kg < 4; ++kg) {
                int d0 = half * 64 + kg * 16 + (lane >> 4) * 8;
                uint32_t qh[4], ql[4];
                ldsm4(qh, s2u(&sm[SQH + (wrow + (lane & 15)) * 136 + d0]));
                ldsm4(ql, s2u(&sm[SQL + (wrow + (lane & 15)) * 136 + d0]));
#pragma unroll
                for (int p = 0; p < 2; ++p) {
                    uint32_t t[4], u[4];
                    int off = lb + (p * 16 + (lane & 15)) * 136 + d0;
                    ldsm4(t, s2u(&sm[off]));
                    ldsm4(u, s2u(&sm[off + 4352]));
                    mma16816(S[2 * p], qh, t[0], t[2]);
                    mma16816(S[2 * p], qh, u[0], u[2]);
                    mma16816(S[2 * p], ql, t[0], t[2]);
                    mma16816(S[2 * p + 1], qh, t[1], t[3]);
                    mma16816(S[2 * p + 1], qh, u[1], u[3]);
                    mma16816(S[2 * p + 1], ql, t[1], t[3]);
                }
            }

            // online softmax in exp2 domain (rows: A = lane>>2, B = +8)
            float mxA = -1e30f, mxB = -1e30f;
#pragma unroll
            for (int ng = 0; ng < 4; ++ng) {
                mxA = fmaxf(mxA, fmaxf(S[ng][0], S[ng][1]));
                mxB = fmaxf(mxB, fmaxf(S[ng][2], S[ng][3]));
            }
            mxA = fmaxf(mxA, __shfl_xor_sync(0xffffffffu, mxA, 1));
            mxA = fmaxf(mxA, __shfl_xor_sync(0xffffffffu, mxA, 2));
            mxB = fmaxf(mxB, __shfl_xor_sync(0xffffffffu, mxB, 1));
            mxB = fmaxf(mxB, __shfl_xor_sync(0xffffffffu, mxB, 2));
            float nmA = fmaxf(mA[half], mxA), nmB = fmaxf(mB[half], mxB);
            float aA = ex2(mA[half] - nmA), aB = ex2(mB[half] - nmB);
            float sA = 0.f, sB = 0.f;
#pragma unroll
            for (int ng = 0; ng < 4; ++ng) {
                S[ng][0] = ex2(S[ng][0] - nmA);
                S[ng][1] = ex2(S[ng][1] - nmA);
                S[ng][2] = ex2(S[ng][2] - nmB);
                S[ng][3] = ex2(S[ng][3] - nmB);
                sA += S[ng][0] + S[ng][1];
                sB += S[ng][2] + S[ng][3];
            }
            sA += __shfl_xor_sync(0xffffffffu, sA, 1);
            sA += __shfl_xor_sync(0xffffffffu, sA, 2);
            sB += __shfl_xor_sync(0xffffffffu, sB, 1);
            sB += __shfl_xor_sync(0xffffffffu, sB, 2);
            lA[half] = lA[half] * aA + sA; mA[half] = nmA;
            lB[half] = lB[half] * aB + sB; mB[half] = nmB;
#pragma unroll
            for (int ng = 0; ng < 16; ++ng) {
                ac[ng][0] *= aA; ac[ng][1] *= aA;
                ac[ng][2] *= aB; ac[ng][3] *= aB;
            }
#pragma unroll
            for (int j = 0; j < 2; ++j) {
                split2(S[2 * j][0], S[2 * j][1], ph[half][j][0], pl[half][j][0]);
                split2(S[2 * j][2], S[2 * j][3], ph[half][j][1], pl[half][j][1]);
                split2(S[2 * j + 1][0], S[2 * j + 1][1], ph[half][j][2], pl[half][j][2]);
                split2(S[2 * j + 1][2], S[2 * j + 1][3], ph[half][j][3], pl[half][j][3]);
            }
        }

        // PV for both halves, V fragments loaded ONCE
#pragma unroll
        for (int kg2 = 0; kg2 < 2; ++kg2) {
#pragma unroll
            for (int np = 0; np < 8; ++np) {
                uint32_t vh[4], vl[4];
                int off = lb + 8704 + (kg2 * 16 + (lane & 15)) * 136 + np * 16 + (lane >> 4) * 8;
                ldsm4t(vh, s2u(&sm[off]));
                ldsm4t(vl, s2u(&sm[off + 4352]));
                mma16816(acc0[2 * np], ph[0][kg2], vh[0], vh[1]);
                mma16816(acc0[2 * np], ph[0][kg2], vl[0], vl[1]);
                mma16816(acc0[2 * np], pl[0][kg2], vh[0], vh[1]);
                mma16816(acc0[2 * np + 1], ph[0][kg2], vh[2], vh[3]);
                mma16816(acc0[2 * np + 1], ph[0][kg2], vl[2], vl[3]);
                mma16816(acc0[2 * np + 1], pl[0][kg2], vh[2], vh[3]);
                mma16816(acc1[2 * np], ph[1][kg2], vh[0], vh[1]);
                mma16816(acc1[2 * np], ph[1][kg2], vl[0], vl[1]);
                mma16816(acc1[2 * np], pl[1][kg2], vh[0], vh[1]);
                mma16816(acc1[2 * np + 1], ph[1][kg2], vh[2], vh[3]);
                mma16816(acc1[2 * np + 1], ph[1][kg2], vl[2], vl[3]);
                mma16816(acc1[2 * np + 1], pl[1][kg2], vh[2], vh[3]);
            }
        }
        __syncthreads();
    }

    // Epilogue: o = acc0/l0 - lam*acc1/l1, per-head LayerNorm over 128 channels.
    float i0A = 1.f / lA[0], i0B = 1.f / lB[0];
    float i1A = lam / lA[1], i1B = lam / lB[1];
    float suA = 0.f, sqA = 0.f, suB = 0.f, sqB = 0.f;
#pragma unroll
    for (int ng = 0; ng < 16; ++ng) {
        float o0 = acc0[ng][0] * i0A - acc1[ng][0] * i1A;
        float o1 = acc0[ng][1] * i0A - acc1[ng][1] * i1A;
        float o2 = acc0[ng][2] * i0B - acc1[ng][2] * i1B;
        float o3 = acc0[ng][3] * i0B - acc1[ng][3] * i1B;
        acc0[ng][0] = o0; acc0[ng][1] = o1; acc0[ng][2] = o2; acc0[ng][3] = o3;
        suA += o0 + o1; sqA += o0 * o0 + o1 * o1;
        suB += o2 + o3; sqB += o2 * o2 + o3 * o3;
    }
    suA += __shfl_xor_sync(0xffffffffu, suA, 1); suA += __shfl_xor_sync(0xffffffffu, suA, 2);
    sqA += __shfl_xor_sync(0xffffffffu, sqA, 1); sqA += __shfl_xor_sync(0xffffffffu, sqA, 2);
    suB += __shfl_xor_sync(0xffffffffu, suB, 1); suB += __shfl_xor_sync(0xffffffffu, suB, 2);
    sqB += __shfl_xor_sync(0xffffffffu, sqB, 1); sqB += __shfl_xor_sync(0xffffffffu, sqB, 2);
    float muA = suA * (1.f / 128.f), muB = suB * (1.f / 128.f);
    float rsA = rsqrtf(sqA * (1.f / 128.f) - muA * muA + 1e-5f);
    float rsB = rsqrtf(sqB * (1.f / 128.f) - muB * muB + 1e-5f);

    int rA = b * NN + q0 + wrow + (lane >> 2);
    int rB = rA + 8;
#pragma unroll
    for (int ng = 0; ng < 16; ++ng) {
        int col = ng * 8 + 2 * (lane & 3);
        float g0 = lng[col], g1 = lng[col + 1];
        float b0 = lnb[col], b1 = lnb[col + 1];
        float y0 = (acc0[ng][0] - muA) * rsA * g0 + b0;
        float y1 = (acc0[ng][1] - muA) * rsA * g1 + b1;
        float y2 = (acc0[ng][2] - muB) * rsB * g0 + b0;
        float y3 = (acc0[ng][3] - muB) * rsB * g1 + b1;
        uint32_t h, l;
        size_t dA = (size_t)rA * EE + hp * 128 + col;
        size_t dB = (size_t)rB * EE + hp * 128 + col;
        split2(y0, y1, h, l);
        *(uint32_t*)&oh_[dA] = h; *(uint32_t*)&ol_[dA] = l;
        split2(y2, y3, h, l);
        *(uint32_t*)&oh_[dB] = h; *(uint32_t*)&ol_[dB] = l;
    }
}

// ---------------------------------------------------------------------------
extern "C" void kernel_launch(void* const* d_in, const int* in_sizes, int n_in,
                              void* d_out, int out_size) {
    const float* x   = (const float*)d_in[0];
    const float* Wq  = (const float*)d_in[1];
    const float* Wk  = (const float*)d_in[2];
    const float* Wv  = (const float*)d_in[3];
    const float* Wo  = (const float*)d_in[4];
    const float* lq1 = (const float*)d_in[5];
    const float* lk1 = (const float*)d_in[6];
    const float* lq2 = (const float*)d_in[7];
    const float* lk2 = (const float*)d_in[8];
    const float* lng = (const float*)d_in[9];
    const float* lnb = (const float*)d_in[10];
    float* out = (float*)d_out;

    bf16 *wbh, *wbl, *xh, *xl, *qh, *ql, *kh, *kl, *vh, *vl, *ah, *al;
    cudaGetSymbolAddress((void**)&wbh, g_wbh);
    cudaGetSymbolAddress((void**)&wbl, g_wbl);
    cudaGetSymbolAddress((void**)&xh, g_xh);
    cudaGetSymbolAddress((void**)&xl, g_xl);
    cudaGetSymbolAddress((void**)&qh, g_qh);
    cudaGetSymbolAddress((void**)&ql, g_ql);
    cudaGetSymbolAddress((void**)&kh, g_kh);
    cudaGetSymbolAddress((void**)&kl, g_kl);
    cudaGetSymbolAddress((void**)&vh, g_vh);
    cudaGetSymbolAddress((void**)&vl, g_vl);
    cudaGetSymbolAddress((void**)&ah, g_ah);
    cudaGetSymbolAddress((void**)&al, g_al);

    wsplit_kernel<<<dim3(1024, 4), 256>>>(Wq, Wk, Wv, Wo);
    xsplit_kernel<<<4096, 256>>>(x);
    lambda_kernel<<<1, 32>>>(lq1, lk1, lq2, lk2);

    cudaFuncSetAttribute(mma_gemm, cudaFuncAttributeMaxDynamicSharedMemorySize, GSM_BYTES);
    cudaFuncSetAttribute(flash_kernel, cudaFuncAttributeMaxDynamicSharedMemorySize, FSM_BYTES);

    const size_t WSZ = (size_t)EE * EE;
    const float LOG2E = 1.4426950408889634f;
    dim3 gg(8, 32);
    // q projection pre-scaled by D^-0.5 * log2(e) so softmax runs in exp2 domain
    mma_gemm<<<gg, 256, GSM_BYTES>>>(xh, xl, wbh + 0 * WSZ, wbl + 0 * WSZ, nullptr, qh, ql, 0.125f * LOG2E, 1);
    mma_gemm<<<gg, 256, GSM_BYTES>>>(xh, xl, wbh + 1 * WSZ, wbl + 1 * WSZ, nullptr, kh, kl, 1.f, 1);
    mma_gemm<<<gg, 256, GSM_BYTES>>>(xh, xl, wbh + 2 * WSZ, wbl + 2 * WSZ, nullptr, vh, vl, 1.f, 1);

    dim3 fg(NN / 64, HH, BB);  // (32, 8, 2)
    flash_kernel<<<fg, 128, FSM_BYTES>>>(qh, ql, kh, kl, vh, vl, lng, lnb, ah, al);

    mma_gemm<<<gg, 256, GSM_BYTES>>>(ah, al, wbh + 3 * WSZ, wbl + 3 * WSZ, out, nullptr, nullptr, 1.f, 0);
}

// round 5
// speedup vs baseline: 4.7558x; 1.2355x over previous
#include <cuda_runtime.h>
#include <cuda_fp16.h>
#include <math.h>
#include <stdint.h>

#define BB 2
#define NN 2048
#define EE 1024
#define HH 8
#define DD 64
#define MM (BB*NN)

typedef __half fp16;

// ---------------- scratch (__device__ globals; no runtime alloc) ----------------
__device__ fp16 g_wbh[4u * EE * EE];
__device__ fp16 g_wbl[4u * EE * EE];
__device__ fp16 g_xh[MM * EE], g_xl[MM * EE];
__device__ fp16 g_qh[MM * EE], g_ql[MM * EE];
__device__ fp16 g_k[MM * EE];          // single-rounded fp16
__device__ fp16 g_v[MM * EE];          // single-rounded fp16
__device__ fp16 g_ah[MM * EE], g_al[MM * EE];
__device__ float g_lambda;

// ---------------- helpers ----------------
__device__ __forceinline__ uint32_t s2u(const void* p) {
    return (uint32_t)__cvta_generic_to_shared(p);
}
__device__ __forceinline__ void ldsm4(uint32_t* r, uint32_t a) {
    asm volatile("ldmatrix.sync.aligned.m8n8.x4.shared.b16 {%0,%1,%2,%3},[%4];\n"
                 : "=r"(r[0]), "=r"(r[1]), "=r"(r[2]), "=r"(r[3]) : "r"(a));
}
__device__ __forceinline__ void ldsm4t(uint32_t* r, uint32_t a) {
    asm volatile("ldmatrix.sync.aligned.m8n8.x4.trans.shared.b16 {%0,%1,%2,%3},[%4];\n"
                 : "=r"(r[0]), "=r"(r[1]), "=r"(r[2]), "=r"(r[3]) : "r"(a));
}
__device__ __forceinline__ void mma16816(float* d, const uint32_t* a, uint32_t b0, uint32_t b1) {
    asm volatile("mma.sync.aligned.m16n8k16.row.col.f32.f16.f16.f32 "
                 "{%0,%1,%2,%3},{%4,%5,%6,%7},{%8,%9},{%0,%1,%2,%3};\n"
                 : "+f"(d[0]), "+f"(d[1]), "+f"(d[2]), "+f"(d[3])
                 : "r"(a[0]), "r"(a[1]), "r"(a[2]), "r"(a[3]), "r"(b0), "r"(b1));
}
__device__ __forceinline__ void cpa16(uint32_t dst, const void* src) {
    asm volatile("cp.async.cg.shared.global [%0], [%1], 16;\n" :: "r"(dst), "l"(src));
}
#define CP_COMMIT asm volatile("cp.async.commit_group;\n")
#define CP_WAIT1  asm volatile("cp.async.wait_group 1;\n")
__device__ __forceinline__ float ex2(float x) {
    float y; asm("ex2.approx.f32 %0,%1;\n" : "=f"(y) : "f"(x)); return y;
}
__device__ __forceinline__ void split2h(float a, float b, uint32_t& hi, uint32_t& lo) {
    __half2 h, l;
    h.x = __float2half_rn(a); h.y = __float2half_rn(b);
    l.x = __float2half_rn(a - __half2float(h.x));
    l.y = __float2half_rn(b - __half2float(h.y));
    hi = *(uint32_t*)&h; lo = *(uint32_t*)&l;
}
__device__ __forceinline__ uint32_t pack2h(float a, float b) {
    __half2 h; h.x = __float2half_rn(a); h.y = __float2half_rn(b);
    return *(uint32_t*)&h;
}

// ---------------- lambda ----------------
__global__ void lambda_kernel(const float* __restrict__ lq1, const float* __restrict__ lk1,
                              const float* __restrict__ lq2, const float* __restrict__ lk2) {
    int t = threadIdx.x;
    float s1 = 0.f, s2 = 0.f;
    for (int i = t; i < DD; i += 32) { s1 += lq1[i] * lk1[i]; s2 += lq2[i] * lk2[i]; }
#pragma unroll
    for (int o = 16; o; o >>= 1) {
        s1 += __shfl_xor_sync(0xffffffffu, s1, o);
        s2 += __shfl_xor_sync(0xffffffffu, s2, o);
    }
    if (t == 0) {
        double lam_init = 0.8 - 0.6 * exp(-0.3 * 12.0);
        g_lambda = expf(s1) - expf(s2) + (float)lam_init;
    }
}

// ---------------- split kernels ----------------
__global__ void wsplit_kernel(const float* __restrict__ W0, const float* __restrict__ W1,
                              const float* __restrict__ W2, const float* __restrict__ W3) {
    const float* W = (blockIdx.y == 0) ? W0 : (blockIdx.y == 1) ? W1 : (blockIdx.y == 2) ? W2 : W3;
    size_t base = (size_t)blockIdx.y * EE * EE;
    size_t i = (size_t)blockIdx.x * 1024 + threadIdx.x * 4;
    float4 v = *(const float4*)&W[i];
    uint32_t h0, l0, h1, l1;
    split2h(v.x, v.y, h0, l0);
    split2h(v.z, v.w, h1, l1);
    uint32_t* oh = (uint32_t*)&g_wbh[base + i];
    uint32_t* ol = (uint32_t*)&g_wbl[base + i];
    oh[0] = h0; oh[1] = h1; ol[0] = l0; ol[1] = l1;
}

__global__ void xsplit_kernel(const float* __restrict__ x) {
    size_t i = (size_t)blockIdx.x * 1024 + threadIdx.x * 4;
    float4 v = *(const float4*)&x[i];
    uint32_t h0, l0, h1, l1;
    split2h(v.x, v.y, h0, l0);
    split2h(v.z, v.w, h1, l1);
    uint32_t* oh = (uint32_t*)&g_xh[i];
    uint32_t* ol = (uint32_t*)&g_xl[i];
    oh[0] = h0; oh[1] = h1; ol[0] = l0; ol[1] = l1;
}

// ---------------- fp16-split MMA GEMM (3-term), cp.async double-buffered ----------------
// smem layout (fp16 elements):
//   A buf b: AH at b*10240, AL at +5120     (128 rows x 32 cols, pitch 40)
//   B buf b: BH at 20480+b*8704, BL at +4352 (32 rows x 128 cols, pitch 136)
#define GSM_ELEMS 37888
#define GSM_BYTES (GSM_ELEMS * 2)

// mode 0: fp32 -> Cf.  mode 1: split fp16 pair -> Ch/Cl.  mode 2: single fp16 -> Ch.
__global__ __launch_bounds__(256, 2) void mma_gemm(const fp16* __restrict__ Ah, const fp16* __restrict__ Al,
                                                   const fp16* __restrict__ Wh, const fp16* __restrict__ Wl,
                                                   float* __restrict__ Cf, fp16* __restrict__ Ch,
                                                   fp16* __restrict__ Cl, float alpha, int mode) {
    extern __shared__ fp16 sg[];
    const int tid = threadIdx.x, lane = tid & 31, wid = tid >> 5;
    const int wm = (wid >> 2) * 64, wn = (wid & 3) * 32;
    const int m0 = blockIdx.y * 128, n0 = blockIdx.x * 128;

    float acc[4][4][4];
#pragma unroll
    for (int i = 0; i < 4; ++i)
#pragma unroll
        for (int j = 0; j < 4; ++j)
#pragma unroll
            for (int q = 0; q < 4; ++q) acc[i][j][q] = 0.f;

    auto copy_tile = [&](int kt, int bu) {
        int ao = bu * 10240, bo = 20480 + bu * 8704;
#pragma unroll
        for (int j = 0; j < 2; ++j) {
            int ch = tid + j * 256;
            int r = ch >> 2, s = (ch & 3) * 8;
            cpa16(s2u(&sg[ao + r * 40 + s]), &Ah[(size_t)(m0 + r) * EE + kt + s]);
            cpa16(s2u(&sg[ao + 5120 + r * 40 + s]), &Al[(size_t)(m0 + r) * EE + kt + s]);
        }
#pragma unroll
        for (int j = 0; j < 2; ++j) {
            int ch = tid + j * 256;
            int r = ch >> 4, s = (ch & 15) * 8;
            cpa16(s2u(&sg[bo + r * 136 + s]), &Wh[(size_t)(kt + r) * EE + n0 + s]);
            cpa16(s2u(&sg[bo + 4352 + r * 136 + s]), &Wl[(size_t)(kt + r) * EE + n0 + s]);
        }
    };

    copy_tile(0, 0);
    CP_COMMIT;

    int bu = 0;
    for (int kt = 0; kt < EE; kt += 32, bu ^= 1) {
        if (kt + 32 < EE) copy_tile(kt + 32, bu ^ 1);
        CP_COMMIT;
        CP_WAIT1;
        __syncthreads();
        int ao = bu * 10240, bo = 20480 + bu * 8704;
#pragma unroll
        for (int kg = 0; kg < 2; ++kg) {
            uint32_t ah[4][4], al[4][4], bh[4][2], bl[4][2];
#pragma unroll
            for (int i = 0; i < 4; ++i) {
                int off = (wm + i * 16 + (lane & 15)) * 40 + kg * 16 + (lane >> 4) * 8;
                ldsm4(ah[i], s2u(&sg[ao + off]));
                ldsm4(al[i], s2u(&sg[ao + 5120 + off]));
            }
#pragma unroll
            for (int p = 0; p < 2; ++p) {
                int off = (kg * 16 + (lane & 15)) * 136 + wn + p * 16 + (lane >> 4) * 8;
                uint32_t t[4], u[4];
                ldsm4t(t, s2u(&sg[bo + off]));
                ldsm4t(u, s2u(&sg[bo + 4352 + off]));
                bh[2 * p][0] = t[0]; bh[2 * p][1] = t[1];
                bh[2 * p + 1][0] = t[2]; bh[2 * p + 1][1] = t[3];
                bl[2 * p][0] = u[0]; bl[2 * p][1] = u[1];
                bl[2 * p + 1][0] = u[2]; bl[2 * p + 1][1] = u[3];
            }
#pragma unroll
            for (int i = 0; i < 4; ++i)
#pragma unroll
                for (int ni = 0; ni < 4; ++ni) {
                    mma16816(acc[i][ni], ah[i], bh[ni][0], bh[ni][1]);
                    mma16816(acc[i][ni], ah[i], bl[ni][0], bl[ni][1]);
                    mma16816(acc[i][ni], al[i], bh[ni][0], bh[ni][1]);
                }
        }
        __syncthreads();
    }

#pragma unroll
    for (int mi = 0; mi < 4; ++mi) {
        int r0 = m0 + wm + mi * 16 + (lane >> 2);
        int r1 = r0 + 8;
#pragma unroll
        for (int ni = 0; ni < 4; ++ni) {
            int col = n0 + wn + ni * 8 + 2 * (lane & 3);
            if (mode == 0) {
                float2 a = make_float2(acc[mi][ni][0], acc[mi][ni][1]);
                float2 b = make_float2(acc[mi][ni][2], acc[mi][ni][3]);
                *(float2*)&Cf[(size_t)r0 * EE + col] = a;
                *(float2*)&Cf[(size_t)r1 * EE + col] = b;
            } else if (mode == 1) {
                uint32_t h, l;
                split2h(acc[mi][ni][0] * alpha, acc[mi][ni][1] * alpha, h, l);
                *(uint32_t*)&Ch[(size_t)r0 * EE + col] = h;
                *(uint32_t*)&Cl[(size_t)r0 * EE + col] = l;
                split2h(acc[mi][ni][2] * alpha, acc[mi][ni][3] * alpha, h, l);
                *(uint32_t*)&Ch[(size_t)r1 * EE + col] = h;
                *(uint32_t*)&Cl[(size_t)r1 * EE + col] = l;
            } else {
                *(uint32_t*)&Ch[(size_t)r0 * EE + col] = pack2h(acc[mi][ni][0], acc[mi][ni][1]);
                *(uint32_t*)&Ch[(size_t)r1 * EE + col] = pack2h(acc[mi][ni][2], acc[mi][ni][3]);
            }
        }
    }
}

// ---------------- differential flash attention + fused LayerNorm ----------------
// CTA: (64 q-rows, head-pair hp, batch b); 4 warps x 16 rows; 32-key tiles,
// double-buffered single-fp16 K/V via cp.async; q/P kept as exact hi/lo pairs.
// smem (fp16 elements): QH 0, QL 8704; KV buf b at 17408+b*8704: K +0, V +4352.
#define SQH 0
#define SQL 8704
#define KVB 17408
#define FSM_ELEMS (17408 + 2 * 8704)
#define FSM_BYTES (FSM_ELEMS * 2)

__global__ __launch_bounds__(128, 2) void flash_kernel(const fp16* __restrict__ qh_, const fp16* __restrict__ ql_,
                                                       const fp16* __restrict__ k_, const fp16* __restrict__ v_,
                                                       const float* __restrict__ lng, const float* __restrict__ lnb,
                                                       fp16* __restrict__ oh_, fp16* __restrict__ ol_) {
    extern __shared__ fp16 sm[];
    const int tid = threadIdx.x, lane = tid & 31, wid = tid >> 5;
    const int b = blockIdx.z, hp = blockIdx.y;
    const int q0 = blockIdx.x * 64;
    const int wrow = wid * 16;
    const float lam = g_lambda;

    auto copy_kv = [&](int kt, int bu) {
        int base = KVB + bu * 8704;
#pragma unroll
        for (int j = 0; j < 4; ++j) {
            int ch = tid + j * 128;
            int r = ch >> 4, s = (ch & 15) * 8;
            size_t src = (size_t)(b * NN + kt + r) * EE + hp * 128 + s;
            cpa16(s2u(&sm[base + r * 136 + s]), &k_[src]);
            cpa16(s2u(&sm[base + 4352 + r * 136 + s]), &v_[src]);
        }
    };

    // Q tile (64 x 128 hi+lo) + first KV tile in one async group
#pragma unroll
    for (int j = 0; j < 8; ++j) {
        int ch = tid + j * 128;
        int r = ch >> 4, s = (ch & 15) * 8;
        size_t src = (size_t)(b * NN + q0 + r) * EE + hp * 128 + s;
        cpa16(s2u(&sm[SQH + r * 136 + s]), &qh_[src]);
        cpa16(s2u(&sm[SQL + r * 136 + s]), &ql_[src]);
    }
    copy_kv(0, 0);
    CP_COMMIT;

    float acc0[16][4], acc1[16][4];
#pragma unroll
    for (int i = 0; i < 16; ++i)
#pragma unroll
        for (int j = 0; j < 4; ++j) { acc0[i][j] = 0.f; acc1[i][j] = 0.f; }
    float mA[2], mB[2], lA[2], lB[2];
    mA[0] = mA[1] = mB[0] = mB[1] = -1e30f;
    lA[0] = lA[1] = lB[0] = lB[1] = 0.f;

    int bu = 0;
    for (int kt = 0; kt < NN; kt += 32, bu ^= 1) {
        if (kt + 32 < NN) copy_kv(kt + 32, bu ^ 1);
        CP_COMMIT;
        CP_WAIT1;
        __syncthreads();
        const int lb = KVB + bu * 8704;

        uint32_t ph[2][2][4], pl[2][2][4];
#pragma unroll
        for (int half = 0; half < 2; ++half) {
            float (*ac)[4] = half ? acc1 : acc0;
            float S[4][4];
#pragma unroll
            for (int i = 0; i < 4; ++i)
#pragma unroll
                for (int j = 0; j < 4; ++j) S[i][j] = 0.f;

            // S = (Qh + Ql) * K over d = half*64 .. +64 (log2e pre-folded in q)
#pragma unroll
            for (int kg = 0; kg < 4; ++kg) {
                int d0 = half * 64 + kg * 16 + (lane >> 4) * 8;
                uint32_t qh[4], ql[4];
                ldsm4(qh, s2u(&sm[SQH + (wrow + (lane & 15)) * 136 + d0]));
                ldsm4(ql, s2u(&sm[SQL + (wrow + (lane & 15)) * 136 + d0]));
#pragma unroll
                for (int p = 0; p < 2; ++p) {
                    uint32_t t[4];
                    ldsm4(t, s2u(&sm[lb + (p * 16 + (lane & 15)) * 136 + d0]));
                    mma16816(S[2 * p], qh, t[0], t[2]);
                    mma16816(S[2 * p], ql, t[0], t[2]);
                    mma16816(S[2 * p + 1], qh, t[1], t[3]);
                    mma16816(S[2 * p + 1], ql, t[1], t[3]);
                }
            }

            // online softmax in exp2 domain (rows: A = lane>>2, B = +8)
            float mxA = -1e30f, mxB = -1e30f;
#pragma unroll
            for (int ng = 0; ng < 4; ++ng) {
                mxA = fmaxf(mxA, fmaxf(S[ng][0], S[ng][1]));
                mxB = fmaxf(mxB, fmaxf(S[ng][2], S[ng][3]));
            }
            mxA = fmaxf(mxA, __shfl_xor_sync(0xffffffffu, mxA, 1));
            mxA = fmaxf(mxA, __shfl_xor_sync(0xffffffffu, mxA, 2));
            mxB = fmaxf(mxB, __shfl_xor_sync(0xffffffffu, mxB, 1));
            mxB = fmaxf(mxB, __shfl_xor_sync(0xffffffffu, mxB, 2));
            float nmA = fmaxf(mA[half], mxA), nmB = fmaxf(mB[half], mxB);
            float aA = ex2(mA[half] - nmA), aB = ex2(mB[half] - nmB);
            float sA = 0.f, sB = 0.f;
#pragma unroll
            for (int ng = 0; ng < 4; ++ng) {
                S[ng][0] = ex2(S[ng][0] - nmA);
                S[ng][1] = ex2(S[ng][1] - nmA);
                S[ng][2] = ex2(S[ng][2] - nmB);
                S[ng][3] = ex2(S[ng][3] - nmB);
                sA += S[ng][0] + S[ng][1];
                sB += S[ng][2] + S[ng][3];
            }
            sA += __shfl_xor_sync(0xffffffffu, sA, 1);
            sA += __shfl_xor_sync(0xffffffffu, sA, 2);
            sB += __shfl_xor_sync(0xffffffffu, sB, 1);
            sB += __shfl_xor_sync(0xffffffffu, sB, 2);
            lA[half] = lA[half] * aA + sA; mA[half] = nmA;
            lB[half] = lB[half] * aB + sB; mB[half] = nmB;
#pragma unroll
            for (int ng = 0; ng < 16; ++ng) {
                ac[ng][0] *= aA; ac[ng][1] *= aA;
                ac[ng][2] *= aB; ac[ng][3] *= aB;
            }
#pragma unroll
            for (int j = 0; j < 2; ++j) {
                split2h(S[2 * j][0], S[2 * j][1], ph[half][j][0], pl[half][j][0]);
                split2h(S[2 * j][2], S[2 * j][3], ph[half][j][1], pl[half][j][1]);
                split2h(S[2 * j + 1][0], S[2 * j + 1][1], ph[half][j][2], pl[half][j][2]);
                split2h(S[2 * j + 1][2], S[2 * j + 1][3], ph[half][j][3], pl[half][j][3]);
            }
        }

        // PV for both halves; V fragments (single fp16) loaded once
#pragma unroll
        for (int kg2 = 0; kg2 < 2; ++kg2) {
#pragma unroll
            for (int np = 0; np < 8; ++np) {
                uint32_t vf[4];
                int off = lb + 4352 + (kg2 * 16 + (lane & 15)) * 136 + np * 16 + (lane >> 4) * 8;
                ldsm4t(vf, s2u(&sm[off]));
                mma16816(acc0[2 * np], ph[0][kg2], vf[0], vf[1]);
                mma16816(acc0[2 * np], pl[0][kg2], vf[0], vf[1]);
                mma16816(acc0[2 * np + 1], ph[0][kg2], vf[2], vf[3]);
                mma16816(acc0[2 * np + 1], pl[0][kg2], vf[2], vf[3]);
                mma16816(acc1[2 * np], ph[1][kg2], vf[0], vf[1]);
                mma16816(acc1[2 * np], pl[1][kg2], vf[0], vf[1]);
                mma16816(acc1[2 * np + 1], ph[1][kg2], vf[2], vf[3]);
                mma16816(acc1[2 * np + 1], pl[1][kg2], vf[2], vf[3]);
            }
        }
        __syncthreads();
    }

    // Epilogue: o = acc0/l0 - lam*acc1/l1, per-head LayerNorm over 128 channels.
    float i0A = 1.f / lA[0], i0B = 1.f / lB[0];
    float i1A = lam / lA[1], i1B = lam / lB[1];
    float suA = 0.f, sqA = 0.f, suB = 0.f, sqB = 0.f;
#pragma unroll
    for (int ng = 0; ng < 16; ++ng) {
        float o0 = acc0[ng][0] * i0A - acc1[ng][0] * i1A;
        float o1 = acc0[ng][1] * i0A - acc1[ng][1] * i1A;
        float o2 = acc0[ng][2] * i0B - acc1[ng][2] * i1B;
        float o3 = acc0[ng][3] * i0B - acc1[ng][3] * i1B;
        acc0[ng][0] = o0; acc0[ng][1] = o1; acc0[ng][2] = o2; acc0[ng][3] = o3;
        suA += o0 + o1; sqA += o0 * o0 + o1 * o1;
        suB += o2 + o3; sqB += o2 * o2 + o3 * o3;
    }
    suA += __shfl_xor_sync(0xffffffffu, suA, 1); suA += __shfl_xor_sync(0xffffffffu, suA, 2);
    sqA += __shfl_xor_sync(0xffffffffu, sqA, 1); sqA += __shfl_xor_sync(0xffffffffu, sqA, 2);
    suB += __shfl_xor_sync(0xffffffffu, suB, 1); suB += __shfl_xor_sync(0xffffffffu, suB, 2);
    sqB += __shfl_xor_sync(0xffffffffu, sqB, 1); sqB += __shfl_xor_sync(0xffffffffu, sqB, 2);
    float muA = suA * (1.f / 128.f), muB = suB * (1.f / 128.f);
    float rsA = rsqrtf(sqA * (1.f / 128.f) - muA * muA + 1e-5f);
    float rsB = rsqrtf(sqB * (1.f / 128.f) - muB * muB + 1e-5f);

    int rA = b * NN + q0 + wrow + (lane >> 2);
    int rB = rA + 8;
#pragma unroll
    for (int ng = 0; ng < 16; ++ng) {
        int col = ng * 8 + 2 * (lane & 3);
        float g0 = lng[col], g1 = lng[col + 1];
        float b0 = lnb[col], b1 = lnb[col + 1];
        float y0 = (acc0[ng][0] - muA) * rsA * g0 + b0;
        float y1 = (acc0[ng][1] - muA) * rsA * g1 + b1;
        float y2 = (acc0[ng][2] - muB) * rsB * g0 + b0;
        float y3 = (acc0[ng][3] - muB) * rsB * g1 + b1;
        uint32_t h, l;
        size_t dA = (size_t)rA * EE + hp * 128 + col;
        size_t dB = (size_t)rB * EE + hp * 128 + col;
        split2h(y0, y1, h, l);
        *(uint32_t*)&oh_[dA] = h; *(uint32_t*)&ol_[dA] = l;
        split2h(y2, y3, h, l);
        *(uint32_t*)&oh_[dB] = h; *(uint32_t*)&ol_[dB] = l;
    }
}

// ---------------------------------------------------------------------------
extern "C" void kernel_launch(void* const* d_in, const int* in_sizes, int n_in,
                              void* d_out, int out_size) {
    const float* x   = (const float*)d_in[0];
    const float* Wq  = (const float*)d_in[1];
    const float* Wk  = (const float*)d_in[2];
    const float* Wv  = (const float*)d_in[3];
    const float* Wo  = (const float*)d_in[4];
    const float* lq1 = (const float*)d_in[5];
    const float* lk1 = (const float*)d_in[6];
    const float* lq2 = (const float*)d_in[7];
    const float* lk2 = (const float*)d_in[8];
    const float* lng = (const float*)d_in[9];
    const float* lnb = (const float*)d_in[10];
    float* out = (float*)d_out;

    fp16 *wbh, *wbl, *xh, *xl, *qh, *ql, *kk, *vv, *ah, *al;
    cudaGetSymbolAddress((void**)&wbh, g_wbh);
    cudaGetSymbolAddress((void**)&wbl, g_wbl);
    cudaGetSymbolAddress((void**)&xh, g_xh);
    cudaGetSymbolAddress((void**)&xl, g_xl);
    cudaGetSymbolAddress((void**)&qh, g_qh);
    cudaGetSymbolAddress((void**)&ql, g_ql);
    cudaGetSymbolAddress((void**)&kk, g_k);
    cudaGetSymbolAddress((void**)&vv, g_v);
    cudaGetSymbolAddress((void**)&ah, g_ah);
    cudaGetSymbolAddress((void**)&al, g_al);

    wsplit_kernel<<<dim3(1024, 4), 256>>>(Wq, Wk, Wv, Wo);
    xsplit_kernel<<<4096, 256>>>(x);
    lambda_kernel<<<1, 32>>>(lq1, lk1, lq2, lk2);

    cudaFuncSetAttribute(mma_gemm, cudaFuncAttributeMaxDynamicSharedMemorySize, GSM_BYTES);
    cudaFuncSetAttribute(flash_kernel, cudaFuncAttributeMaxDynamicSharedMemorySize, FSM_BYTES);

    const size_t WSZ = (size_t)EE * EE;
    const float LOG2E = 1.4426950408889634f;
    dim3 gg(8, 32);
    // q: split pair, pre-scaled by D^-0.5 * log2(e); k,v: single rounded fp16
    mma_gemm<<<gg, 256, GSM_BYTES>>>(xh, xl, wbh + 0 * WSZ, wbl + 0 * WSZ, nullptr, qh, ql, 0.125f * LOG2E, 1);
    mma_gemm<<<gg, 256, GSM_BYTES>>>(xh, xl, wbh + 1 * WSZ, wbl + 1 * WSZ, nullptr, kk, nullptr, 1.f, 2);
    mma_gemm<<<gg, 256, GSM_BYTES>>>(xh, xl, wbh + 2 * WSZ, wbl + 2 * WSZ, nullptr, vv, nullptr, 1.f, 2);

    dim3 fg(NN / 64, HH, BB);  // (32, 8, 2)
    flash_kernel<<<fg, 128, FSM_BYTES>>>(qh, ql, kk, vv, lng, lnb, ah, al);

    mma_gemm<<<gg, 256, GSM_BYTES>>>(ah, al, wbh + 3 * WSZ, wbl + 3 * WSZ, out, nullptr, nullptr, 1.f, 0);
}

// round 6
// speedup vs baseline: 6.3218x; 1.3293x over previous
#include <cuda_runtime.h>
#include <cuda_fp16.h>
#include <math.h>
#include <stdint.h>

#define BB 2
#define NN 2048
#define EE 1024
#define HH 8
#define DD 64
#define MM (BB*NN)

typedef __half fp16;

// ---------------- scratch (__device__ globals; no runtime alloc) ----------------
__device__ fp16 g_wbh[4u * EE * EE];
__device__ fp16 g_wbl[4u * EE * EE];
__device__ fp16 g_x16[MM * EE];                 // single-rounded x
__device__ fp16 g_qh[MM * EE], g_ql[MM * EE];   // q as exact pair
__device__ fp16 g_k[MM * EE];                   // single-rounded
__device__ fp16 g_v[MM * EE];                   // single-rounded
__device__ fp16 g_a16[MM * EE];                 // single-rounded attention output
__device__ float g_lambda;

// ---------------- helpers ----------------
__device__ __forceinline__ uint32_t s2u(const void* p) {
    return (uint32_t)__cvta_generic_to_shared(p);
}
__device__ __forceinline__ void ldsm4(uint32_t* r, uint32_t a) {
    asm volatile("ldmatrix.sync.aligned.m8n8.x4.shared.b16 {%0,%1,%2,%3},[%4];\n"
                 : "=r"(r[0]), "=r"(r[1]), "=r"(r[2]), "=r"(r[3]) : "r"(a));
}
__device__ __forceinline__ void ldsm4t(uint32_t* r, uint32_t a) {
    asm volatile("ldmatrix.sync.aligned.m8n8.x4.trans.shared.b16 {%0,%1,%2,%3},[%4];\n"
                 : "=r"(r[0]), "=r"(r[1]), "=r"(r[2]), "=r"(r[3]) : "r"(a));
}
__device__ __forceinline__ void mma16816(float* d, const uint32_t* a, uint32_t b0, uint32_t b1) {
    asm volatile("mma.sync.aligned.m16n8k16.row.col.f32.f16.f16.f32 "
                 "{%0,%1,%2,%3},{%4,%5,%6,%7},{%8,%9},{%0,%1,%2,%3};\n"
                 : "+f"(d[0]), "+f"(d[1]), "+f"(d[2]), "+f"(d[3])
                 : "r"(a[0]), "r"(a[1]), "r"(a[2]), "r"(a[3]), "r"(b0), "r"(b1));
}
__device__ __forceinline__ void cpa16(uint32_t dst, const void* src) {
    asm volatile("cp.async.cg.shared.global [%0], [%1], 16;\n" :: "r"(dst), "l"(src));
}
#define CP_COMMIT asm volatile("cp.async.commit_group;\n")
#define CP_WAIT1  asm volatile("cp.async.wait_group 1;\n")
__device__ __forceinline__ float ex2(float x) {
    float y; asm("ex2.approx.f32 %0,%1;\n" : "=f"(y) : "f"(x)); return y;
}
__device__ __forceinline__ void split2h(float a, float b, uint32_t& hi, uint32_t& lo) {
    __half2 h, l;
    h.x = __float2half_rn(a); h.y = __float2half_rn(b);
    l.x = __float2half_rn(a - __half2float(h.x));
    l.y = __float2half_rn(b - __half2float(h.y));
    hi = *(uint32_t*)&h; lo = *(uint32_t*)&l;
}
__device__ __forceinline__ uint32_t pack2h(float a, float b) {
    __half2 h; h.x = __float2half_rn(a); h.y = __float2half_rn(b);
    return *(uint32_t*)&h;
}

// ---------------- lambda ----------------
__global__ void lambda_kernel(const float* __restrict__ lq1, const float* __restrict__ lk1,
                              const float* __restrict__ lq2, const float* __restrict__ lk2) {
    int t = threadIdx.x;
    float s1 = 0.f, s2 = 0.f;
    for (int i = t; i < DD; i += 32) { s1 += lq1[i] * lk1[i]; s2 += lq2[i] * lk2[i]; }
#pragma unroll
    for (int o = 16; o; o >>= 1) {
        s1 += __shfl_xor_sync(0xffffffffu, s1, o);
        s2 += __shfl_xor_sync(0xffffffffu, s2, o);
    }
    if (t == 0) {
        double lam_init = 0.8 - 0.6 * exp(-0.3 * 12.0);
        g_lambda = expf(s1) - expf(s2) + (float)lam_init;
    }
}

// ---------------- weight split (exact fp16 pairs) ----------------
__global__ void wsplit_kernel(const float* __restrict__ W0, const float* __restrict__ W1,
                              const float* __restrict__ W2, const float* __restrict__ W3) {
    const float* W = (blockIdx.y == 0) ? W0 : (blockIdx.y == 1) ? W1 : (blockIdx.y == 2) ? W2 : W3;
    size_t base = (size_t)blockIdx.y * EE * EE;
    size_t i = (size_t)blockIdx.x * 1024 + threadIdx.x * 4;
    float4 v = *(const float4*)&W[i];
    uint32_t h0, l0, h1, l1;
    split2h(v.x, v.y, h0, l0);
    split2h(v.z, v.w, h1, l1);
    uint32_t* oh = (uint32_t*)&g_wbh[base + i];
    uint32_t* ol = (uint32_t*)&g_wbl[base + i];
    oh[0] = h0; oh[1] = h1; ol[0] = l0; ol[1] = l1;
}

// ---------------- x -> single-rounded fp16 ----------------
__global__ void xround_kernel(const float* __restrict__ x) {
    size_t i = (size_t)blockIdx.x * 1024 + threadIdx.x * 4;
    float4 v = *(const float4*)&x[i];
    uint32_t* o = (uint32_t*)&g_x16[i];
    o[0] = pack2h(v.x, v.y);
    o[1] = pack2h(v.z, v.w);
}

// ---------------- 2-term MMA GEMM: C = A_fp16 @ (Wh + Wl), cp.async double-buffered ----------------
// smem (fp16 elems): A buf b at b*5120 (128x32, pitch 40);
//                    B buf b at 10240 + b*8704: BH +0, BL +4352 (32x128, pitch 136)
#define GSM_ELEMS 27648
#define GSM_BYTES (GSM_ELEMS * 2)

// mode 0: fp32 -> Cf.  mode 1: split fp16 pair -> Ch/Cl (alpha applied).  mode 2: single fp16 -> Ch.
__global__ __launch_bounds__(256, 2) void mma_gemm(const fp16* __restrict__ A,
                                                   const fp16* __restrict__ Wh, const fp16* __restrict__ Wl,
                                                   float* __restrict__ Cf, fp16* __restrict__ Ch,
                                                   fp16* __restrict__ Cl, float alpha, int mode) {
    extern __shared__ fp16 sg[];
    const int tid = threadIdx.x, lane = tid & 31, wid = tid >> 5;
    const int wm = (wid >> 2) * 64, wn = (wid & 3) * 32;
    const int m0 = blockIdx.y * 128, n0 = blockIdx.x * 128;

    float acc[4][4][4];
#pragma unroll
    for (int i = 0; i < 4; ++i)
#pragma unroll
        for (int j = 0; j < 4; ++j)
#pragma unroll
            for (int q = 0; q < 4; ++q) acc[i][j][q] = 0.f;

    auto copy_tile = [&](int kt, int bu) {
        int ao = bu * 5120, bo = 10240 + bu * 8704;
        {
            int ch = tid;                      // A: 512 chunks of 8 elems, 2 per thread
            int r = ch >> 2, s = (ch & 3) * 8;
            cpa16(s2u(&sg[ao + r * 40 + s]), &A[(size_t)(m0 + r) * EE + kt + s]);
            ch = tid + 256;
            r = ch >> 2; s = (ch & 3) * 8;
            cpa16(s2u(&sg[ao + r * 40 + s]), &A[(size_t)(m0 + r) * EE + kt + s]);
        }
#pragma unroll
        for (int j = 0; j < 2; ++j) {
            int ch = tid + j * 256;
            int r = ch >> 4, s = (ch & 15) * 8;
            cpa16(s2u(&sg[bo + r * 136 + s]), &Wh[(size_t)(kt + r) * EE + n0 + s]);
            cpa16(s2u(&sg[bo + 4352 + r * 136 + s]), &Wl[(size_t)(kt + r) * EE + n0 + s]);
        }
    };

    copy_tile(0, 0);
    CP_COMMIT;

    int bu = 0;
    for (int kt = 0; kt < EE; kt += 32, bu ^= 1) {
        if (kt + 32 < EE) copy_tile(kt + 32, bu ^ 1);
        CP_COMMIT;
        CP_WAIT1;
        __syncthreads();
        int ao = bu * 5120, bo = 10240 + bu * 8704;
#pragma unroll
        for (int kg = 0; kg < 2; ++kg) {
            uint32_t ah[4][4], bh[4][2], bl[4][2];
#pragma unroll
            for (int i = 0; i < 4; ++i) {
                int off = (wm + i * 16 + (lane & 15)) * 40 + kg * 16 + (lane >> 4) * 8;
                ldsm4(ah[i], s2u(&sg[ao + off]));
            }
#pragma unroll
            for (int p = 0; p < 2; ++p) {
                int off = (kg * 16 + (lane & 15)) * 136 + wn + p * 16 + (lane >> 4) * 8;
                uint32_t t[4], u[4];
                ldsm4t(t, s2u(&sg[bo + off]));
                ldsm4t(u, s2u(&sg[bo + 4352 + off]));
                bh[2 * p][0] = t[0]; bh[2 * p][1] = t[1];
                bh[2 * p + 1][0] = t[2]; bh[2 * p + 1][1] = t[3];
                bl[2 * p][0] = u[0]; bl[2 * p][1] = u[1];
                bl[2 * p + 1][0] = u[2]; bl[2 * p + 1][1] = u[3];
            }
#pragma unroll
            for (int i = 0; i < 4; ++i)
#pragma unroll
                for (int ni = 0; ni < 4; ++ni) {
                    mma16816(acc[i][ni], ah[i], bh[ni][0], bh[ni][1]);
                    mma16816(acc[i][ni], ah[i], bl[ni][0], bl[ni][1]);
                }
        }
        __syncthreads();
    }

#pragma unroll
    for (int mi = 0; mi < 4; ++mi) {
        int r0 = m0 + wm + mi * 16 + (lane >> 2);
        int r1 = r0 + 8;
#pragma unroll
        for (int ni = 0; ni < 4; ++ni) {
            int col = n0 + wn + ni * 8 + 2 * (lane & 3);
            if (mode == 0) {
                float2 a = make_float2(acc[mi][ni][0], acc[mi][ni][1]);
                float2 b = make_float2(acc[mi][ni][2], acc[mi][ni][3]);
                *(float2*)&Cf[(size_t)r0 * EE + col] = a;
                *(float2*)&Cf[(size_t)r1 * EE + col] = b;
            } else if (mode == 1) {
                uint32_t h, l;
                split2h(acc[mi][ni][0] * alpha, acc[mi][ni][1] * alpha, h, l);
                *(uint32_t*)&Ch[(size_t)r0 * EE + col] = h;
                *(uint32_t*)&Cl[(size_t)r0 * EE + col] = l;
                split2h(acc[mi][ni][2] * alpha, acc[mi][ni][3] * alpha, h, l);
                *(uint32_t*)&Ch[(size_t)r1 * EE + col] = h;
                *(uint32_t*)&Cl[(size_t)r1 * EE + col] = l;
            } else {
                *(uint32_t*)&Ch[(size_t)r0 * EE + col] = pack2h(acc[mi][ni][0], acc[mi][ni][1]);
                *(uint32_t*)&Ch[(size_t)r1 * EE + col] = pack2h(acc[mi][ni][2], acc[mi][ni][3]);
            }
        }
    }
}

// ---------------- differential flash attention + fused LayerNorm ----------------
// CTA: (64 q-rows, head-pair hp, batch b); 4 warps x 16 rows; 32-key tiles,
// double-buffered single-fp16 K/V; q exact pair; P single-rounded fp16.
// smem (fp16 elems): QH 0, QL 8704; KV buf b at 17408+b*8704: K +0, V +4352.
#define SQH 0
#define SQL 8704
#define KVB 17408
#define FSM_ELEMS (17408 + 2 * 8704)
#define FSM_BYTES (FSM_ELEMS * 2)

__global__ __launch_bounds__(128, 2) void flash_kernel(const fp16* __restrict__ qh_, const fp16* __restrict__ ql_,
                                                       const fp16* __restrict__ k_, const fp16* __restrict__ v_,
                                                       const float* __restrict__ lng, const float* __restrict__ lnb,
                                                       fp16* __restrict__ o_) {
    extern __shared__ fp16 sm[];
    const int tid = threadIdx.x, lane = tid & 31, wid = tid >> 5;
    const int b = blockIdx.z, hp = blockIdx.y;
    const int q0 = blockIdx.x * 64;
    const int wrow = wid * 16;
    const float lam = g_lambda;

    auto copy_kv = [&](int kt, int bu) {
        int base = KVB + bu * 8704;
#pragma unroll
        for (int j = 0; j < 4; ++j) {
            int ch = tid + j * 128;
            int r = ch >> 4, s = (ch & 15) * 8;
            size_t src = (size_t)(b * NN + kt + r) * EE + hp * 128 + s;
            cpa16(s2u(&sm[base + r * 136 + s]), &k_[src]);
            cpa16(s2u(&sm[base + 4352 + r * 136 + s]), &v_[src]);
        }
    };

#pragma unroll
    for (int j = 0; j < 8; ++j) {
        int ch = tid + j * 128;
        int r = ch >> 4, s = (ch & 15) * 8;
        size_t src = (size_t)(b * NN + q0 + r) * EE + hp * 128 + s;
        cpa16(s2u(&sm[SQH + r * 136 + s]), &qh_[src]);
        cpa16(s2u(&sm[SQL + r * 136 + s]), &ql_[src]);
    }
    copy_kv(0, 0);
    CP_COMMIT;

    float acc0[16][4], acc1[16][4];
#pragma unroll
    for (int i = 0; i < 16; ++i)
#pragma unroll
        for (int j = 0; j < 4; ++j) { acc0[i][j] = 0.f; acc1[i][j] = 0.f; }
    float mA[2], mB[2], lA[2], lB[2];
    mA[0] = mA[1] = mB[0] = mB[1] = -1e30f;
    lA[0] = lA[1] = lB[0] = lB[1] = 0.f;

    int bu = 0;
    for (int kt = 0; kt < NN; kt += 32, bu ^= 1) {
        if (kt + 32 < NN) copy_kv(kt + 32, bu ^ 1);
        CP_COMMIT;
        CP_WAIT1;
        __syncthreads();
        const int lb = KVB + bu * 8704;

        uint32_t ph[2][2][4];
#pragma unroll
        for (int half = 0; half < 2; ++half) {
            float (*ac)[4] = half ? acc1 : acc0;
            float S[4][4];
#pragma unroll
            for (int i = 0; i < 4; ++i)
#pragma unroll
                for (int j = 0; j < 4; ++j) S[i][j] = 0.f;

            // S = (Qh + Ql) * K over d = half*64 .. +64 (log2e pre-folded into q)
#pragma unroll
            for (int kg = 0; kg < 4; ++kg) {
                int d0 = half * 64 + kg * 16 + (lane >> 4) * 8;
                uint32_t qh[4], ql[4];
                ldsm4(qh, s2u(&sm[SQH + (wrow + (lane & 15)) * 136 + d0]));
                ldsm4(ql, s2u(&sm[SQL + (wrow + (lane & 15)) * 136 + d0]));
#pragma unroll
                for (int p = 0; p < 2; ++p) {
                    uint32_t t[4];
                    ldsm4(t, s2u(&sm[lb + (p * 16 + (lane & 15)) * 136 + d0]));
                    mma16816(S[2 * p], qh, t[0], t[2]);
                    mma16816(S[2 * p], ql, t[0], t[2]);
                    mma16816(S[2 * p + 1], qh, t[1], t[3]);
                    mma16816(S[2 * p + 1], ql, t[1], t[3]);
                }
            }

            // online softmax in exp2 domain (rows: A = lane>>2, B = +8)
            float mxA = -1e30f, mxB = -1e30f;
#pragma unroll
            for (int ng = 0; ng < 4; ++ng) {
                mxA = fmaxf(mxA, fmaxf(S[ng][0], S[ng][1]));
                mxB = fmaxf(mxB, fmaxf(S[ng][2], S[ng][3]));
            }
            mxA = fmaxf(mxA, __shfl_xor_sync(0xffffffffu, mxA, 1));
            mxA = fmaxf(mxA, __shfl_xor_sync(0xffffffffu, mxA, 2));
            mxB = fmaxf(mxB, __shfl_xor_sync(0xffffffffu, mxB, 1));
            mxB = fmaxf(mxB, __shfl_xor_sync(0xffffffffu, mxB, 2));
            float nmA = fmaxf(mA[half], mxA), nmB = fmaxf(mB[half], mxB);
            float aA = ex2(mA[half] - nmA), aB = ex2(mB[half] - nmB);
            float sA = 0.f, sB = 0.f;
#pragma unroll
            for (int ng = 0; ng < 4; ++ng) {
                S[ng][0] = ex2(S[ng][0] - nmA);
                S[ng][1] = ex2(S[ng][1] - nmA);
                S[ng][2] = ex2(S[ng][2] - nmB);
                S[ng][3] = ex2(S[ng][3] - nmB);
                sA += S[ng][0] + S[ng][1];
                sB += S[ng][2] + S[ng][3];
            }
            sA += __shfl_xor_sync(0xffffffffu, sA, 1);
            sA += __shfl_xor_sync(0xffffffffu, sA, 2);
            sB += __shfl_xor_sync(0xffffffffu, sB, 1);
            sB += __shfl_xor_sync(0xffffffffu, sB, 2);
            lA[half] = lA[half] * aA + sA; mA[half] = nmA;
            lB[half] = lB[half] * aB + sB; mB[half] = nmB;
#pragma unroll
            for (int ng = 0; ng < 16; ++ng) {
                ac[ng][0] *= aA; ac[ng][1] *= aA;
                ac[ng][2] *= aB; ac[ng][3] *= aB;
            }
#pragma unroll
            for (int j = 0; j < 2; ++j) {
                ph[half][j][0] = pack2h(S[2 * j][0], S[2 * j][1]);
                ph[half][j][1] = pack2h(S[2 * j][2], S[2 * j][3]);
                ph[half][j][2] = pack2h(S[2 * j + 1][0], S[2 * j + 1][1]);
                ph[half][j][3] = pack2h(S[2 * j + 1][2], S[2 * j + 1][3]);
            }
        }

        // PV for both halves; V fragments loaded once, P single fp16
#pragma unroll
        for (int kg2 = 0; kg2 < 2; ++kg2) {
#pragma unroll
            for (int np = 0; np < 8; ++np) {
                uint32_t vf[4];
                int off = lb + 4352 + (kg2 * 16 + (lane & 15)) * 136 + np * 16 + (lane >> 4) * 8;
                ldsm4t(vf, s2u(&sm[off]));
                mma16816(acc0[2 * np], ph[0][kg2], vf[0], vf[1]);
                mma16816(acc0[2 * np + 1], ph[0][kg2], vf[2], vf[3]);
                mma16816(acc1[2 * np], ph[1][kg2], vf[0], vf[1]);
                mma16816(acc1[2 * np + 1], ph[1][kg2], vf[2], vf[3]);
            }
        }
        __syncthreads();
    }

    // Epilogue: o = acc0/l0 - lam*acc1/l1, per-head LayerNorm over 128 channels.
    float i0A = 1.f / lA[0], i0B = 1.f / lB[0];
    float i1A = lam / lA[1], i1B = lam / lB[1];
    float suA = 0.f, sqA = 0.f, suB = 0.f, sqB = 0.f;
#pragma unroll
    for (int ng = 0; ng < 16; ++ng) {
        float o0 = acc0[ng][0] * i0A - acc1[ng][0] * i1A;
        float o1 = acc0[ng][1] * i0A - acc1[ng][1] * i1A;
        float o2 = acc0[ng][2] * i0B - acc1[ng][2] * i1B;
        float o3 = acc0[ng][3] * i0B - acc1[ng][3] * i1B;
        acc0[ng][0] = o0; acc0[ng][1] = o1; acc0[ng][2] = o2; acc0[ng][3] = o3;
        suA += o0 + o1; sqA += o0 * o0 + o1 * o1;
        suB += o2 + o3; sqB += o2 * o2 + o3 * o3;
    }
    suA += __shfl_xor_sync(0xffffffffu, suA, 1); suA += __shfl_xor_sync(0xffffffffu, suA, 2);
    sqA += __shfl_xor_sync(0xffffffffu, sqA, 1); sqA += __shfl_xor_sync(0xffffffffu, sqA, 2);
    suB += __shfl_xor_sync(0xffffffffu, suB, 1); suB += __shfl_xor_sync(0xffffffffu, suB, 2);
    sqB += __shfl_xor_sync(0xffffffffu, sqB, 1); sqB += __shfl_xor_sync(0xffffffffu, sqB, 2);
    float muA = suA * (1.f / 128.f), muB = suB * (1.f / 128.f);
    float rsA = rsqrtf(sqA * (1.f / 128.f) - muA * muA + 1e-5f);
    float rsB = rsqrtf(sqB * (1.f / 128.f) - muB * muB + 1e-5f);

    int rA = b * NN + q0 + wrow + (lane >> 2);
    int rB = rA + 8;
#pragma unroll
    for (int ng = 0; ng < 16; ++ng) {
        int col = ng * 8 + 2 * (lane & 3);
        float g0 = lng[col], g1 = lng[col + 1];
        float b0 = lnb[col], b1 = lnb[col + 1];
        float y0 = (acc0[ng][0] - muA) * rsA * g0 + b0;
        float y1 = (acc0[ng][1] - muA) * rsA * g1 + b1;
        float y2 = (acc0[ng][2] - muB) * rsB * g0 + b0;
        float y3 = (acc0[ng][3] - muB) * rsB * g1 + b1;
        size_t dA = (size_t)rA * EE + hp * 128 + col;
        size_t dB = (size_t)rB * EE + hp * 128 + col;
        *(uint32_t*)&o_[dA] = pack2h(y0, y1);
        *(uint32_t*)&o_[dB] = pack2h(y2, y3);
    }
}

// ---------------------------------------------------------------------------
extern "C" void kernel_launch(void* const* d_in, const int* in_sizes, int n_in,
                              void* d_out, int out_size) {
    const float* x   = (const float*)d_in[0];
    const float* Wq  = (const float*)d_in[1];
    const float* Wk  = (const float*)d_in[2];
    const float* Wv  = (const float*)d_in[3];
    const float* Wo  = (const float*)d_in[4];
    const float* lq1 = (const float*)d_in[5];
    const float* lk1 = (const float*)d_in[6];
    const float* lq2 = (const float*)d_in[7];
    const float* lk2 = (const float*)d_in[8];
    const float* lng = (const float*)d_in[9];
    const float* lnb = (const float*)d_in[10];
    float* out = (float*)d_out;

    fp16 *wbh, *wbl, *x16, *qh, *ql, *kk, *vv, *a16;
    cudaGetSymbolAddress((void**)&wbh, g_wbh);
    cudaGetSymbolAddress((void**)&wbl, g_wbl);
    cudaGetSymbolAddress((void**)&x16, g_x16);
    cudaGetSymbolAddress((void**)&qh, g_qh);
    cudaGetSymbolAddress((void**)&ql, g_ql);
    cudaGetSymbolAddress((void**)&kk, g_k);
    cudaGetSymbolAddress((void**)&vv, g_v);
    cudaGetSymbolAddress((void**)&a16, g_a16);

    wsplit_kernel<<<dim3(1024, 4), 256>>>(Wq, Wk, Wv, Wo);
    xround_kernel<<<4096, 256>>>(x);
    lambda_kernel<<<1, 32>>>(lq1, lk1, lq2, lk2);

    cudaFuncSetAttribute(mma_gemm, cudaFuncAttributeMaxDynamicSharedMemorySize, GSM_BYTES);
    cudaFuncSetAttribute(flash_kernel, cudaFuncAttributeMaxDynamicSharedMemorySize, FSM_BYTES);

    const size_t WSZ = (size_t)EE * EE;
    const float LOG2E = 1.4426950408889634f;
    dim3 gg(8, 32);
    // q: exact pair, pre-scaled by D^-0.5 * log2(e); k,v: single fp16
    mma_gemm<<<gg, 256, GSM_BYTES>>>(x16, wbh + 0 * WSZ, wbl + 0 * WSZ, nullptr, qh, ql, 0.125f * LOG2E, 1);
    mma_gemm<<<gg, 256, GSM_BYTES>>>(x16, wbh + 1 * WSZ, wbl + 1 * WSZ, nullptr, kk, nullptr, 1.f, 2);
    mma_gemm<<<gg, 256, GSM_BYTES>>>(x16, wbh + 2 * WSZ, wbl + 2 * WSZ, nullptr, vv, nullptr, 1.f, 2);

    dim3 fg(NN / 64, HH, BB);  // (32, 8, 2)
    flash_kernel<<<fg, 128, FSM_BYTES>>>(qh, ql, kk, vv, lng, lnb, a16);

    mma_gemm<<<gg, 256, GSM_BYTES>>>(a16, wbh + 3 * WSZ, wbl + 3 * WSZ, out, nullptr, nullptr, 1.f, 0);
}

// round 7
// speedup vs baseline: 6.8886x; 1.0896x over previous
#include <cuda_runtime.h>
#include <cuda_fp16.h>
#include <math.h>
#include <stdint.h>

#define BB 2
#define NN 2048
#define EE 1024
#define HH 8
#define DD 64
#define MM (BB*NN)
#define N3 (3*EE)

typedef __half fp16;

// ---------------- scratch (__device__ globals; no runtime alloc) ----------------
__device__ fp16 g_wqkvh[(size_t)EE * N3];   // [k=1024][n=3072] hi  (Wq|Wk|Wv)
__device__ fp16 g_wqkvl[(size_t)EE * N3];   // lo
__device__ fp16 g_woh[(size_t)EE * EE], g_wol[(size_t)EE * EE];
__device__ fp16 g_x16[MM * EE];
__device__ fp16 g_qh[MM * EE], g_ql[MM * EE];
__device__ fp16 g_k[MM * EE];
__device__ fp16 g_v[MM * EE];
__device__ fp16 g_a16[MM * EE];
__device__ float g_lambda;

// ---------------- helpers ----------------
__device__ __forceinline__ uint32_t s2u(const void* p) {
    return (uint32_t)__cvta_generic_to_shared(p);
}
__device__ __forceinline__ void ldsm4(uint32_t* r, uint32_t a) {
    asm volatile("ldmatrix.sync.aligned.m8n8.x4.shared.b16 {%0,%1,%2,%3},[%4];\n"
                 : "=r"(r[0]), "=r"(r[1]), "=r"(r[2]), "=r"(r[3]) : "r"(a));
}
__device__ __forceinline__ void ldsm4t(uint32_t* r, uint32_t a) {
    asm volatile("ldmatrix.sync.aligned.m8n8.x4.trans.shared.b16 {%0,%1,%2,%3},[%4];\n"
                 : "=r"(r[0]), "=r"(r[1]), "=r"(r[2]), "=r"(r[3]) : "r"(a));
}
__device__ __forceinline__ void mma16816(float* d, const uint32_t* a, uint32_t b0, uint32_t b1) {
    asm volatile("mma.sync.aligned.m16n8k16.row.col.f32.f16.f16.f32 "
                 "{%0,%1,%2,%3},{%4,%5,%6,%7},{%8,%9},{%0,%1,%2,%3};\n"
                 : "+f"(d[0]), "+f"(d[1]), "+f"(d[2]), "+f"(d[3])
                 : "r"(a[0]), "r"(a[1]), "r"(a[2]), "r"(a[3]), "r"(b0), "r"(b1));
}
__device__ __forceinline__ void cpa16(uint32_t dst, const void* src) {
    asm volatile("cp.async.cg.shared.global [%0], [%1], 16;\n" :: "r"(dst), "l"(src));
}
#define CP_COMMIT asm volatile("cp.async.commit_group;\n")
#define CP_WAIT1  asm volatile("cp.async.wait_group 1;\n")
__device__ __forceinline__ float ex2(float x) {
    float y; asm("ex2.approx.f32 %0,%1;\n" : "=f"(y) : "f"(x)); return y;
}
__device__ __forceinline__ void split2h(float a, float b, uint32_t& hi, uint32_t& lo) {
    __half2 h, l;
    h.x = __float2half_rn(a); h.y = __float2half_rn(b);
    l.x = __float2half_rn(a - __half2float(h.x));
    l.y = __float2half_rn(b - __half2float(h.y));
    hi = *(uint32_t*)&h; lo = *(uint32_t*)&l;
}
__device__ __forceinline__ uint32_t pack2h(float a, float b) {
    __half2 h; h.x = __float2half_rn(a); h.y = __float2half_rn(b);
    return *(uint32_t*)&h;
}

// ---------------- lambda ----------------
__global__ void lambda_kernel(const float* __restrict__ lq1, const float* __restrict__ lk1,
                              const float* __restrict__ lq2, const float* __restrict__ lk2) {
    int t = threadIdx.x;
    float s1 = 0.f, s2 = 0.f;
    for (int i = t; i < DD; i += 32) { s1 += lq1[i] * lk1[i]; s2 += lq2[i] * lk2[i]; }
#pragma unroll
    for (int o = 16; o; o >>= 1) {
        s1 += __shfl_xor_sync(0xffffffffu, s1, o);
        s2 += __shfl_xor_sync(0xffffffffu, s2, o);
    }
    if (t == 0) {
        double lam_init = 0.8 - 0.6 * exp(-0.3 * 12.0);
        g_lambda = expf(s1) - expf(s2) + (float)lam_init;
    }
}

// ---------------- weight split: Wq|Wk|Wv -> fused [1024][3072] pair; Wo -> [1024][1024] pair ----------------
__global__ void wsplit_kernel(const float* __restrict__ W0, const float* __restrict__ W1,
                              const float* __restrict__ W2, const float* __restrict__ W3) {
    int m = blockIdx.y;  // 0..3
    const float* W = (m == 0) ? W0 : (m == 1) ? W1 : (m == 2) ? W2 : W3;
    size_t i = (size_t)blockIdx.x * 1024 + threadIdx.x * 4;
    float4 v = *(const float4*)&W[i];
    uint32_t h0, l0, h1, l1;
    split2h(v.x, v.y, h0, l0);
    split2h(v.z, v.w, h1, l1);
    size_t r = i >> 10, c = i & 1023;
    uint32_t *oh, *ol;
    if (m < 3) {
        size_t d = r * N3 + m * EE + c;
        oh = (uint32_t*)&g_wqkvh[d]; ol = (uint32_t*)&g_wqkvl[d];
    } else {
        oh = (uint32_t*)&g_woh[i]; ol = (uint32_t*)&g_wol[i];
    }
    oh[0] = h0; oh[1] = h1; ol[0] = l0; ol[1] = l1;
}

__global__ void xround_kernel(const float* __restrict__ x) {
    size_t i = (size_t)blockIdx.x * 1024 + threadIdx.x * 4;
    float4 v = *(const float4*)&x[i];
    uint32_t* o = (uint32_t*)&g_x16[i];
    o[0] = pack2h(v.x, v.y);
    o[1] = pack2h(v.z, v.w);
}

// ============ shared GEMM mainloop (BK=64, 128x128 CTA tile, 2-term weights) ============
// smem layout (fp16 elems), per buf (stride 26624): A 128x64 pitch 72 at +0 (9216),
// Bh 64x128 pitch 136 at +9216 (8704), Bl at +17920 (8704). 2 bufs = 53248 elems.
#define GSM_ELEMS 53248
#define GSM_BYTES (GSM_ELEMS * 2)

#define GEMM_MAINLOOP(LDW)                                                                   \
    float acc[4][4][4];                                                                       \
    _Pragma("unroll") for (int i = 0; i < 4; ++i)                                             \
        _Pragma("unroll") for (int j = 0; j < 4; ++j)                                         \
            _Pragma("unroll") for (int q = 0; q < 4; ++q) acc[i][j][q] = 0.f;                 \
    auto copy_tile = [&](int kt, int bu) {                                                    \
        int base = bu * 26624;                                                                \
        _Pragma("unroll") for (int j = 0; j < 4; ++j) {                                       \
            int ch = tid + j * 256;                                                           \
            int r = ch >> 3, s = (ch & 7) * 8;                                                \
            cpa16(s2u(&sg[base + r * 72 + s]), &A[(size_t)(m0 + r) * EE + kt + s]);           \
        }                                                                                     \
        _Pragma("unroll") for (int j = 0; j < 4; ++j) {                                       \
            int ch = tid + j * 256;                                                           \
            int r = ch >> 4, s = (ch & 15) * 8;                                               \
            cpa16(s2u(&sg[base + 9216 + r * 136 + s]), &Wh[(size_t)(kt + r) * (LDW) + n0 + s]); \
            cpa16(s2u(&sg[base + 17920 + r * 136 + s]), &Wl[(size_t)(kt + r) * (LDW) + n0 + s]); \
        }                                                                                     \
    };                                                                                        \
    copy_tile(0, 0);                                                                          \
    CP_COMMIT;                                                                                \
    int bu = 0;                                                                               \
    for (int kt = 0; kt < EE; kt += 64, bu ^= 1) {                                            \
        if (kt + 64 < EE) copy_tile(kt + 64, bu ^ 1);                                         \
        CP_COMMIT;                                                                            \
        CP_WAIT1;                                                                             \
        __syncthreads();                                                                      \
        int ao = bu * 26624, bo = ao + 9216;                                                  \
        _Pragma("unroll") for (int kg = 0; kg < 4; ++kg) {                                    \
            uint32_t ah[4][4], bh[4][2], bl[4][2];                                            \
            _Pragma("unroll") for (int i = 0; i < 4; ++i) {                                   \
                int off = (wm + i * 16 + (lane & 15)) * 72 + kg * 16 + (lane >> 4) * 8;       \
                ldsm4(ah[i], s2u(&sg[ao + off]));                                             \
            }                                                                                 \
            _Pragma("unroll") for (int p = 0; p < 2; ++p) {                                   \
                int off = (kg * 16 + (lane & 15)) * 136 + wn + p * 16 + (lane >> 4) * 8;      \
                uint32_t t[4], u[4];                                                          \
                ldsm4t(t, s2u(&sg[bo + off]));                                                \
                ldsm4t(u, s2u(&sg[bo + 8704 + off]));                                         \
                bh[2 * p][0] = t[0]; bh[2 * p][1] = t[1];                                     \
                bh[2 * p + 1][0] = t[2]; bh[2 * p + 1][1] = t[3];                             \
                bl[2 * p][0] = u[0]; bl[2 * p][1] = u[1];                                     \
                bl[2 * p + 1][0] = u[2]; bl[2 * p + 1][1] = u[3];                             \
            }                                                                                 \
            _Pragma("unroll") for (int i = 0; i < 4; ++i)                                     \
                _Pragma("unroll") for (int ni = 0; ni < 4; ++ni) {                            \
                    mma16816(acc[i][ni], ah[i], bh[ni][0], bh[ni][1]);                        \
                    mma16816(acc[i][ni], ah[i], bl[ni][0], bl[ni][1]);                        \
                }                                                                             \
        }                                                                                     \
        __syncthreads();                                                                      \
    }

// ---------------- fused QKV GEMM: C[4096,3072] = x16 @ (Wh+Wl); per-section epilogue ----------------
__global__ __launch_bounds__(256, 2) void qkv_gemm(const fp16* __restrict__ A,
                                                   const fp16* __restrict__ Wh, const fp16* __restrict__ Wl,
                                                   fp16* __restrict__ Qh, fp16* __restrict__ Ql,
                                                   fp16* __restrict__ K, fp16* __restrict__ V,
                                                   float alpha_q) {
    extern __shared__ fp16 sg[];
    const int tid = threadIdx.x, lane = tid & 31, wid = tid >> 5;
    const int wm = (wid >> 2) * 64, wn = (wid & 3) * 32;
    const int m0 = blockIdx.y * 128, n0 = blockIdx.x * 128;

    GEMM_MAINLOOP(N3)

    const int sec = blockIdx.x >> 3;               // 0=q, 1=k, 2=v
    const int nbase = n0 - sec * EE;
#pragma unroll
    for (int mi = 0; mi < 4; ++mi) {
        int r0 = m0 + wm + mi * 16 + (lane >> 2);
        int r1 = r0 + 8;
#pragma unroll
        for (int ni = 0; ni < 4; ++ni) {
            int col = nbase + wn + ni * 8 + 2 * (lane & 3);
            if (sec == 0) {
                uint32_t h, l;
                split2h(acc[mi][ni][0] * alpha_q, acc[mi][ni][1] * alpha_q, h, l);
                *(uint32_t*)&Qh[(size_t)r0 * EE + col] = h;
                *(uint32_t*)&Ql[(size_t)r0 * EE + col] = l;
                split2h(acc[mi][ni][2] * alpha_q, acc[mi][ni][3] * alpha_q, h, l);
                *(uint32_t*)&Qh[(size_t)r1 * EE + col] = h;
                *(uint32_t*)&Ql[(size_t)r1 * EE + col] = l;
            } else if (sec == 1) {
                *(uint32_t*)&K[(size_t)r0 * EE + col] = pack2h(acc[mi][ni][0], acc[mi][ni][1]);
                *(uint32_t*)&K[(size_t)r1 * EE + col] = pack2h(acc[mi][ni][2], acc[mi][ni][3]);
            } else {
                *(uint32_t*)&V[(size_t)r0 * EE + col] = pack2h(acc[mi][ni][0], acc[mi][ni][1]);
                *(uint32_t*)&V[(size_t)r1 * EE + col] = pack2h(acc[mi][ni][2], acc[mi][ni][3]);
            }
        }
    }
}

// ---------------- output GEMM: out[4096,1024] fp32 = a16 @ (Woh+Wol) ----------------
__global__ __launch_bounds__(256, 2) void out_gemm(const fp16* __restrict__ A,
                                                   const fp16* __restrict__ Wh, const fp16* __restrict__ Wl,
                                                   float* __restrict__ Cf) {
    extern __shared__ fp16 sg[];
    const int tid = threadIdx.x, lane = tid & 31, wid = tid >> 5;
    const int wm = (wid >> 2) * 64, wn = (wid & 3) * 32;
    const int m0 = blockIdx.y * 128, n0 = blockIdx.x * 128;

    GEMM_MAINLOOP(EE)

#pragma unroll
    for (int mi = 0; mi < 4; ++mi) {
        int r0 = m0 + wm + mi * 16 + (lane >> 2);
        int r1 = r0 + 8;
#pragma unroll
        for (int ni = 0; ni < 4; ++ni) {
            int col = n0 + wn + ni * 8 + 2 * (lane & 3);
            *(float2*)&Cf[(size_t)r0 * EE + col] = make_float2(acc[mi][ni][0], acc[mi][ni][1]);
            *(float2*)&Cf[(size_t)r1 * EE + col] = make_float2(acc[mi][ni][2], acc[mi][ni][3]);
        }
    }
}

// ---------------- differential flash attention + fused LayerNorm (64-key tiles) ----------------
// CTA: (64 q-rows, head-pair hp, batch b); 4 warps x 16 rows; 64-key tiles double-buffered.
// smem (fp16 elems): QH 0 (64x136), QL 8704; KV buf b at 17408+b*17408: K +0, V +8704.
#define SQH 0
#define SQL 8704
#define KVB 17408
#define FSM_ELEMS (17408 + 2 * 17408)
#define FSM_BYTES (FSM_ELEMS * 2)

__global__ __launch_bounds__(128, 2) void flash_kernel(const fp16* __restrict__ qh_, const fp16* __restrict__ ql_,
                                                       const fp16* __restrict__ k_, const fp16* __restrict__ v_,
                                                       const float* __restrict__ lng, const float* __restrict__ lnb,
                                                       fp16* __restrict__ o_) {
    extern __shared__ fp16 sm[];
    const int tid = threadIdx.x, lane = tid & 31, wid = tid >> 5;
    const int b = blockIdx.z, hp = blockIdx.y;
    const int q0 = blockIdx.x * 64;
    const int wrow = wid * 16;
    const float lam = g_lambda;

    auto copy_kv = [&](int kt, int bu) {
        int base = KVB + bu * 17408;
#pragma unroll
        for (int j = 0; j < 8; ++j) {
            int ch = tid + j * 128;
            int r = ch >> 4, s = (ch & 15) * 8;
            size_t src = (size_t)(b * NN + kt + r) * EE + hp * 128 + s;
            cpa16(s2u(&sm[base + r * 136 + s]), &k_[src]);
            cpa16(s2u(&sm[base + 8704 + r * 136 + s]), &v_[src]);
        }
    };

#pragma unroll
    for (int j = 0; j < 8; ++j) {
        int ch = tid + j * 128;
        int r = ch >> 4, s = (ch & 15) * 8;
        size_t src = (size_t)(b * NN + q0 + r) * EE + hp * 128 + s;
        cpa16(s2u(&sm[SQH + r * 136 + s]), &qh_[src]);
        cpa16(s2u(&sm[SQL + r * 136 + s]), &ql_[src]);
    }
    copy_kv(0, 0);
    CP_COMMIT;

    float acc0[16][4], acc1[16][4];
#pragma unroll
    for (int i = 0; i < 16; ++i)
#pragma unroll
        for (int j = 0; j < 4; ++j) { acc0[i][j] = 0.f; acc1[i][j] = 0.f; }
    float mA[2], mB[2], lA[2], lB[2];
    mA[0] = mA[1] = mB[0] = mB[1] = -1e30f;
    lA[0] = lA[1] = lB[0] = lB[1] = 0.f;

    int bu = 0;
    for (int kt = 0; kt < NN; kt += 64, bu ^= 1) {
        if (kt + 64 < NN) copy_kv(kt + 64, bu ^ 1);
        CP_COMMIT;
        CP_WAIT1;
        __syncthreads();
        const int lb = KVB + bu * 17408;

        uint32_t ph[2][4][4];
#pragma unroll
        for (int half = 0; half < 2; ++half) {
            float (*ac)[4] = half ? acc1 : acc0;
            float S[8][4];
#pragma unroll
            for (int i = 0; i < 8; ++i)
#pragma unroll
                for (int j = 0; j < 4; ++j) S[i][j] = 0.f;

            // S = (Qh + Ql) * K over d = half*64 .. +64 (log2e pre-folded into q)
#pragma unroll
            for (int kg = 0; kg < 4; ++kg) {
                int d0 = half * 64 + kg * 16 + (lane >> 4) * 8;
                uint32_t qh[4], ql[4];
                ldsm4(qh, s2u(&sm[SQH + (wrow + (lane & 15)) * 136 + d0]));
                ldsm4(ql, s2u(&sm[SQL + (wrow + (lane & 15)) * 136 + d0]));
#pragma unroll
                for (int p = 0; p < 4; ++p) {
                    uint32_t t[4];
                    ldsm4(t, s2u(&sm[lb + (p * 16 + (lane & 15)) * 136 + d0]));
                    mma16816(S[2 * p], qh, t[0], t[2]);
                    mma16816(S[2 * p], ql, t[0], t[2]);
                    mma16816(S[2 * p + 1], qh, t[1], t[3]);
                    mma16816(S[2 * p + 1], ql, t[1], t[3]);
                }
            }

            // online softmax over 64 keys, exp2 domain (rows: A = lane>>2, B = +8)
            float mxA = -1e30f, mxB = -1e30f;
#pragma unroll
            for (int ng = 0; ng < 8; ++ng) {
                mxA = fmaxf(mxA, fmaxf(S[ng][0], S[ng][1]));
                mxB = fmaxf(mxB, fmaxf(S[ng][2], S[ng][3]));
            }
            mxA = fmaxf(mxA, __shfl_xor_sync(0xffffffffu, mxA, 1));
            mxA = fmaxf(mxA, __shfl_xor_sync(0xffffffffu, mxA, 2));
            mxB = fmaxf(mxB, __shfl_xor_sync(0xffffffffu, mxB, 1));
            mxB = fmaxf(mxB, __shfl_xor_sync(0xffffffffu, mxB, 2));
            float nmA = fmaxf(mA[half], mxA), nmB = fmaxf(mB[half], mxB);
            float aA = ex2(mA[half] - nmA), aB = ex2(mB[half] - nmB);
            float sA = 0.f, sB = 0.f;
#pragma unroll
            for (int ng = 0; ng < 8; ++ng) {
                S[ng][0] = ex2(S[ng][0] - nmA);
                S[ng][1] = ex2(S[ng][1] - nmA);
                S[ng][2] = ex2(S[ng][2] - nmB);
                S[ng][3] = ex2(S[ng][3] - nmB);
                sA += S[ng][0] + S[ng][1];
                sB += S[ng][2] + S[ng][3];
            }
            sA += __shfl_xor_sync(0xffffffffu, sA, 1);
            sA += __shfl_xor_sync(0xffffffffu, sA, 2);
            sB += __shfl_xor_sync(0xffffffffu, sB, 1);
            sB += __shfl_xor_sync(0xffffffffu, sB, 2);
            lA[half] = lA[half] * aA + sA; mA[half] = nmA;
            lB[half] = lB[half] * aB + sB; mB[half] = nmB;
#pragma unroll
            for (int ng = 0; ng < 16; ++ng) {
                ac[ng][0] *= aA; ac[ng][1] *= aA;
                ac[ng][2] *= aB; ac[ng][3] *= aB;
            }
#pragma unroll
            for (int j = 0; j < 4; ++j) {
                ph[half][j][0] = pack2h(S[2 * j][0], S[2 * j][1]);
                ph[half][j][1] = pack2h(S[2 * j][2], S[2 * j][3]);
                ph[half][j][2] = pack2h(S[2 * j + 1][0], S[2 * j + 1][1]);
                ph[half][j][3] = pack2h(S[2 * j + 1][2], S[2 * j + 1][3]);
            }
        }

        // PV for both halves; V fragments loaded once
#pragma unroll
        for (int kg2 = 0; kg2 < 4; ++kg2) {
#pragma unroll
            for (int np = 0; np < 8; ++np) {
                uint32_t vf[4];
                int off = lb + 8704 + (kg2 * 16 + (lane & 15)) * 136 + np * 16 + (lane >> 4) * 8;
                ldsm4t(vf, s2u(&sm[off]));
                mma16816(acc0[2 * np], ph[0][kg2], vf[0], vf[1]);
                mma16816(acc0[2 * np + 1], ph[0][kg2], vf[2], vf[3]);
                mma16816(acc1[2 * np], ph[1][kg2], vf[0], vf[1]);
                mma16816(acc1[2 * np + 1], ph[1][kg2], vf[2], vf[3]);
            }
        }
        __syncthreads();
    }

    // Epilogue: o = acc0/l0 - lam*acc1/l1, per-head LayerNorm over 128 channels.
    float i0A = 1.f / lA[0], i0B = 1.f / lB[0];
    float i1A = lam / lA[1], i1B = lam / lB[1];
    float suA = 0.f, sqA = 0.f, suB = 0.f, sqB = 0.f;
#pragma unroll
    for (int ng = 0; ng < 16; ++ng) {
        float o0 = acc0[ng][0] * i0A - acc1[ng][0] * i1A;
        float o1 = acc0[ng][1] * i0A - acc1[ng][1] * i1A;
        float o2 = acc0[ng][2] * i0B - acc1[ng][2] * i1B;
        float o3 = acc0[ng][3] * i0B - acc1[ng][3] * i1B;
        acc0[ng][0] = o0; acc0[ng][1] = o1; acc0[ng][2] = o2; acc0[ng][3] = o3;
        suA += o0 + o1; sqA += o0 * o0 + o1 * o1;
        suB += o2 + o3; sqB += o2 * o2 + o3 * o3;
    }
    suA += __shfl_xor_sync(0xffffffffu, suA, 1); suA += __shfl_xor_sync(0xffffffffu, suA, 2);
    sqA += __shfl_xor_sync(0xffffffffu, sqA, 1); sqA += __shfl_xor_sync(0xffffffffu, sqA, 2);
    suB += __shfl_xor_sync(0xffffffffu, suB, 1); suB += __shfl_xor_sync(0xffffffffu, suB, 2);
    sqB += __shfl_xor_sync(0xffffffffu, sqB, 1); sqB += __shfl_xor_sync(0xffffffffu, sqB, 2);
    float muA = suA * (1.f / 128.f), muB = suB * (1.f / 128.f);
    float rsA = rsqrtf(sqA * (1.f / 128.f) - muA * muA + 1e-5f);
    float rsB = rsqrtf(sqB * (1.f / 128.f) - muB * muB + 1e-5f);

    int rA = b * NN + q0 + wrow + (lane >> 2);
    int rB = rA + 8;
#pragma unroll
    for (int ng = 0; ng < 16; ++ng) {
        int col = ng * 8 + 2 * (lane & 3);
        float g0 = lng[col], g1 = lng[col + 1];
        float b0 = lnb[col], b1 = lnb[col + 1];
        float y0 = (acc0[ng][0] - muA) * rsA * g0 + b0;
        float y1 = (acc0[ng][1] - muA) * rsA * g1 + b1;
        float y2 = (acc0[ng][2] - muB) * rsB * g0 + b0;
        float y3 = (acc0[ng][3] - muB) * rsB * g1 + b1;
        size_t dA = (size_t)rA * EE + hp * 128 + col;
        size_t dB = (size_t)rB * EE + hp * 128 + col;
        *(uint32_t*)&o_[dA] = pack2h(y0, y1);
        *(uint32_t*)&o_[dB] = pack2h(y2, y3);
    }
}

// ---------------------------------------------------------------------------
extern "C" void kernel_launch(void* const* d_in, const int* in_sizes, int n_in,
                              void* d_out, int out_size) {
    const float* x   = (const float*)d_in[0];
    const float* Wq  = (const float*)d_in[1];
    const float* Wk  = (const float*)d_in[2];
    const float* Wv  = (const float*)d_in[3];
    const float* Wo  = (const float*)d_in[4];
    const float* lq1 = (const float*)d_in[5];
    const float* lk1 = (const float*)d_in[6];
    const float* lq2 = (const float*)d_in[7];
    const float* lk2 = (const float*)d_in[8];
    const float* lng = (const float*)d_in[9];
    const float* lnb = (const float*)d_in[10];
    float* out = (float*)d_out;

    fp16 *wqkvh, *wqkvl, *woh, *wol, *x16, *qh, *ql, *kk, *vv, *a16;
    cudaGetSymbolAddress((void**)&wqkvh, g_wqkvh);
    cudaGetSymbolAddress((void**)&wqkvl, g_wqkvl);
    cudaGetSymbolAddress((void**)&woh, g_woh);
    cudaGetSymbolAddress((void**)&wol, g_wol);
    cudaGetSymbolAddress((void**)&x16, g_x16);
    cudaGetSymbolAddress((void**)&qh, g_qh);
    cudaGetSymbolAddress((void**)&ql, g_ql);
    cudaGetSymbolAddress((void**)&kk, g_k);
    cudaGetSymbolAddress((void**)&vv, g_v);
    cudaGetSymbolAddress((void**)&a16, g_a16);

    wsplit_kernel<<<dim3(1024, 4), 256>>>(Wq, Wk, Wv, Wo);
    xround_kernel<<<4096, 256>>>(x);
    lambda_kernel<<<1, 32>>>(lq1, lk1, lq2, lk2);

    cudaFuncSetAttribute(qkv_gemm, cudaFuncAttributeMaxDynamicSharedMemorySize, GSM_BYTES);
    cudaFuncSetAttribute(out_gemm, cudaFuncAttributeMaxDynamicSharedMemorySize, GSM_BYTES);
    cudaFuncSetAttribute(flash_kernel, cudaFuncAttributeMaxDynamicSharedMemorySize, FSM_BYTES);

    const float LOG2E = 1.4426950408889634f;
    qkv_gemm<<<dim3(24, 32), 256, GSM_BYTES>>>(x16, wqkvh, wqkvl, qh, ql, kk, vv, 0.125f * LOG2E);

    dim3 fg(NN / 64, HH, BB);  // (32, 8, 2)
    flash_kernel<<<fg, 128, FSM_BYTES>>>(qh, ql, kk, vv, lng, lnb, a16);

    out_gemm<<<dim3(8, 32), 256, GSM_BYTES>>>(a16, woh, wol, out);
}

// round 8
// speedup vs baseline: 7.1013x; 1.0309x over previous
#include <cuda_runtime.h>
#include <cuda_fp16.h>
#include <math.h>
#include <stdint.h>

#define BB 2
#define NN 2048
#define EE 1024
#define HH 8
#define DD 64
#define MM (BB*NN)
#define N3 (3*EE)

typedef __half fp16;

// ---------------- scratch (__device__ globals; no runtime alloc) ----------------
__device__ fp16 g_wqkvh[(size_t)EE * N3];   // [k=1024][n=3072] hi  (Wq|Wk|Wv)
__device__ fp16 g_wqkvl[(size_t)EE * N3];   // lo
__device__ fp16 g_woh[(size_t)EE * EE], g_wol[(size_t)EE * EE];
__device__ fp16 g_x16[MM * EE];
__device__ fp16 g_qh[MM * EE], g_ql[MM * EE];
__device__ fp16 g_k[MM * EE];
__device__ fp16 g_v[MM * EE];
__device__ fp16 g_a16[MM * EE];
__device__ float g_lambda;

// ---------------- helpers ----------------
__device__ __forceinline__ uint32_t s2u(const void* p) {
    return (uint32_t)__cvta_generic_to_shared(p);
}
__device__ __forceinline__ void ldsm4(uint32_t* r, uint32_t a) {
    asm volatile("ldmatrix.sync.aligned.m8n8.x4.shared.b16 {%0,%1,%2,%3},[%4];\n"
                 : "=r"(r[0]), "=r"(r[1]), "=r"(r[2]), "=r"(r[3]) : "r"(a));
}
__device__ __forceinline__ void ldsm4t(uint32_t* r, uint32_t a) {
    asm volatile("ldmatrix.sync.aligned.m8n8.x4.trans.shared.b16 {%0,%1,%2,%3},[%4];\n"
                 : "=r"(r[0]), "=r"(r[1]), "=r"(r[2]), "=r"(r[3]) : "r"(a));
}
__device__ __forceinline__ void mma16816(float* d, const uint32_t* a, uint32_t b0, uint32_t b1) {
    asm volatile("mma.sync.aligned.m16n8k16.row.col.f32.f16.f16.f32 "
                 "{%0,%1,%2,%3},{%4,%5,%6,%7},{%8,%9},{%0,%1,%2,%3};\n"
                 : "+f"(d[0]), "+f"(d[1]), "+f"(d[2]), "+f"(d[3])
                 : "r"(a[0]), "r"(a[1]), "r"(a[2]), "r"(a[3]), "r"(b0), "r"(b1));
}
__device__ __forceinline__ void cpa16(uint32_t dst, const void* src) {
    asm volatile("cp.async.cg.shared.global [%0], [%1], 16;\n" :: "r"(dst), "l"(src));
}
#define CP_COMMIT asm volatile("cp.async.commit_group;\n")
#define CP_WAIT1  asm volatile("cp.async.wait_group 1;\n")
__device__ __forceinline__ float ex2(float x) {
    float y; asm("ex2.approx.f32 %0,%1;\n" : "=f"(y) : "f"(x)); return y;
}
// pack (a -> lo, b -> hi) to fp16x2 and take exp2 of both halves in one MUFU op
__device__ __forceinline__ uint32_t exp2pack(float a, float b) {
    uint32_t p;
    asm("cvt.rn.f16x2.f32 %0, %1, %2;\n" : "=r"(p) : "f"(b), "f"(a));
    asm("ex2.approx.f16x2 %0, %0;\n" : "+r"(p));
    return p;
}
__device__ __forceinline__ void split2h(float a, float b, uint32_t& hi, uint32_t& lo) {
    __half2 h, l;
    h.x = __float2half_rn(a); h.y = __float2half_rn(b);
    l.x = __float2half_rn(a - __half2float(h.x));
    l.y = __float2half_rn(b - __half2float(h.y));
    hi = *(uint32_t*)&h; lo = *(uint32_t*)&l;
}
__device__ __forceinline__ uint32_t pack2h(float a, float b) {
    __half2 h; h.x = __float2half_rn(a); h.y = __float2half_rn(b);
    return *(uint32_t*)&h;
}

// ---------------- lambda ----------------
__global__ void lambda_kernel(const float* __restrict__ lq1, const float* __restrict__ lk1,
                              const float* __restrict__ lq2, const float* __restrict__ lk2) {
    int t = threadIdx.x;
    float s1 = 0.f, s2 = 0.f;
    for (int i = t; i < DD; i += 32) { s1 += lq1[i] * lk1[i]; s2 += lq2[i] * lk2[i]; }
#pragma unroll
    for (int o = 16; o; o >>= 1) {
        s1 += __shfl_xor_sync(0xffffffffu, s1, o);
        s2 += __shfl_xor_sync(0xffffffffu, s2, o);
    }
    if (t == 0) {
        double lam_init = 0.8 - 0.6 * exp(-0.3 * 12.0);
        g_lambda = expf(s1) - expf(s2) + (float)lam_init;
    }
}

// ---------------- weight split: Wq|Wk|Wv -> fused [1024][3072] pair; Wo -> [1024][1024] pair ----------------
__global__ void wsplit_kernel(const float* __restrict__ W0, const float* __restrict__ W1,
                              const float* __restrict__ W2, const float* __restrict__ W3) {
    int m = blockIdx.y;  // 0..3
    const float* W = (m == 0) ? W0 : (m == 1) ? W1 : (m == 2) ? W2 : W3;
    size_t i = (size_t)blockIdx.x * 1024 + threadIdx.x * 4;
    float4 v = *(const float4*)&W[i];
    uint32_t h0, l0, h1, l1;
    split2h(v.x, v.y, h0, l0);
    split2h(v.z, v.w, h1, l1);
    size_t r = i >> 10, c = i & 1023;
    uint32_t *oh, *ol;
    if (m < 3) {
        size_t d = r * N3 + m * EE + c;
        oh = (uint32_t*)&g_wqkvh[d]; ol = (uint32_t*)&g_wqkvl[d];
    } else {
        oh = (uint32_t*)&g_woh[i]; ol = (uint32_t*)&g_wol[i];
    }
    oh[0] = h0; oh[1] = h1; ol[0] = l0; ol[1] = l1;
}

__global__ void xround_kernel(const float* __restrict__ x) {
    size_t i = (size_t)blockIdx.x * 1024 + threadIdx.x * 4;
    float4 v = *(const float4*)&x[i];
    uint32_t* o = (uint32_t*)&g_x16[i];
    o[0] = pack2h(v.x, v.y);
    o[1] = pack2h(v.z, v.w);
}

// ============ shared GEMM mainloop (BK=64, 128x128 CTA tile, 2-term weights) ============
// smem layout (fp16 elems), per buf (stride 26624): A 128x64 pitch 72 at +0 (9216),
// Bh 64x128 pitch 136 at +9216 (8704), Bl at +17920 (8704). 2 bufs = 53248 elems.
#define GSM_ELEMS 53248
#define GSM_BYTES (GSM_ELEMS * 2)

#define GEMM_MAINLOOP(LDW)                                                                   \
    float acc[4][4][4];                                                                       \
    _Pragma("unroll") for (int i = 0; i < 4; ++i)                                             \
        _Pragma("unroll") for (int j = 0; j < 4; ++j)                                         \
            _Pragma("unroll") for (int q = 0; q < 4; ++q) acc[i][j][q] = 0.f;                 \
    auto copy_tile = [&](int kt, int bu) {                                                    \
        int base = bu * 26624;                                                                \
        _Pragma("unroll") for (int j = 0; j < 4; ++j) {                                       \
            int ch = tid + j * 256;                                                           \
            int r = ch >> 3, s = (ch & 7) * 8;                                                \
            cpa16(s2u(&sg[base + r * 72 + s]), &A[(size_t)(m0 + r) * EE + kt + s]);           \
        }                                                                                     \
        _Pragma("unroll") for (int j = 0; j < 4; ++j) {                                       \
            int ch = tid + j * 256;                                                           \
            int r = ch >> 4, s = (ch & 15) * 8;                                               \
            cpa16(s2u(&sg[base + 9216 + r * 136 + s]), &Wh[(size_t)(kt + r) * (LDW) + n0 + s]); \
            cpa16(s2u(&sg[base + 17920 + r * 136 + s]), &Wl[(size_t)(kt + r) * (LDW) + n0 + s]); \
        }                                                                                     \
    };                                                                                        \
    copy_tile(0, 0);                                                                          \
    CP_COMMIT;                                                                                \
    int bu = 0;                                                                               \
    for (int kt = 0; kt < EE; kt += 64, bu ^= 1) {                                            \
        if (kt + 64 < EE) copy_tile(kt + 64, bu ^ 1);                                         \
        CP_COMMIT;                                                                            \
        CP_WAIT1;                                                                             \
        __syncthreads();                                                                      \
        int ao = bu * 26624, bo = ao + 9216;                                                  \
        _Pragma("unroll") for (int kg = 0; kg < 4; ++kg) {                                    \
            uint32_t ah[4][4], bh[4][2], bl[4][2];                                            \
            _Pragma("unroll") for (int i = 0; i < 4; ++i) {                                   \
                int off = (wm + i * 16 + (lane & 15)) * 72 + kg * 16 + (lane >> 4) * 8;       \
                ldsm4(ah[i], s2u(&sg[ao + off]));                                             \
            }                                                                                 \
            _Pragma("unroll") for (int p = 0; p < 2; ++p) {                                   \
                int off = (kg * 16 + (lane & 15)) * 136 + wn + p * 16 + (lane >> 4) * 8;      \
                uint32_t t[4], u[4];                                                          \
                ldsm4t(t, s2u(&sg[bo + off]));                                                \
                ldsm4t(u, s2u(&sg[bo + 8704 + off]));                                         \
                bh[2 * p][0] = t[0]; bh[2 * p][1] = t[1];                                     \
                bh[2 * p + 1][0] = t[2]; bh[2 * p + 1][1] = t[3];                             \
                bl[2 * p][0] = u[0]; bl[2 * p][1] = u[1];                                     \
                bl[2 * p + 1][0] = u[2]; bl[2 * p + 1][1] = u[3];                             \
            }                                                                                 \
            _Pragma("unroll") for (int i = 0; i < 4; ++i)                                     \
                _Pragma("unroll") for (int ni = 0; ni < 4; ++ni) {                            \
                    mma16816(acc[i][ni], ah[i], bh[ni][0], bh[ni][1]);                        \
                    mma16816(acc[i][ni], ah[i], bl[ni][0], bl[ni][1]);                        \
                }                                                                             \
        }                                                                                     \
        __syncthreads();                                                                      \
    }

// ---------------- fused QKV GEMM: C[4096,3072] = x16 @ (Wh+Wl); per-section epilogue ----------------
__global__ __launch_bounds__(256, 2) void qkv_gemm(const fp16* __restrict__ A,
                                                   const fp16* __restrict__ Wh, const fp16* __restrict__ Wl,
                                                   fp16* __restrict__ Qh, fp16* __restrict__ Ql,
                                                   fp16* __restrict__ K, fp16* __restrict__ V,
                                                   float alpha_q) {
    extern __shared__ fp16 sg[];
    const int tid = threadIdx.x, lane = tid & 31, wid = tid >> 5;
    const int wm = (wid >> 2) * 64, wn = (wid & 3) * 32;
    const int m0 = blockIdx.y * 128, n0 = blockIdx.x * 128;

    GEMM_MAINLOOP(N3)

    const int sec = blockIdx.x >> 3;               // 0=q, 1=k, 2=v
    const int nbase = n0 - sec * EE;
#pragma unroll
    for (int mi = 0; mi < 4; ++mi) {
        int r0 = m0 + wm + mi * 16 + (lane >> 2);
        int r1 = r0 + 8;
#pragma unroll
        for (int ni = 0; ni < 4; ++ni) {
            int col = nbase + wn + ni * 8 + 2 * (lane & 3);
            if (sec == 0) {
                uint32_t h, l;
                split2h(acc[mi][ni][0] * alpha_q, acc[mi][ni][1] * alpha_q, h, l);
                *(uint32_t*)&Qh[(size_t)r0 * EE + col] = h;
                *(uint32_t*)&Ql[(size_t)r0 * EE + col] = l;
                split2h(acc[mi][ni][2] * alpha_q, acc[mi][ni][3] * alpha_q, h, l);
                *(uint32_t*)&Qh[(size_t)r1 * EE + col] = h;
                *(uint32_t*)&Ql[(size_t)r1 * EE + col] = l;
            } else if (sec == 1) {
                *(uint32_t*)&K[(size_t)r0 * EE + col] = pack2h(acc[mi][ni][0], acc[mi][ni][1]);
                *(uint32_t*)&K[(size_t)r1 * EE + col] = pack2h(acc[mi][ni][2], acc[mi][ni][3]);
            } else {
                *(uint32_t*)&V[(size_t)r0 * EE + col] = pack2h(acc[mi][ni][0], acc[mi][ni][1]);
                *(uint32_t*)&V[(size_t)r1 * EE + col] = pack2h(acc[mi][ni][2], acc[mi][ni][3]);
            }
        }
    }
}

// ---------------- output GEMM: out[4096,1024] fp32 = a16 @ (Woh+Wol) ----------------
__global__ __launch_bounds__(256, 2) void out_gemm(const fp16* __restrict__ A,
                                                   const fp16* __restrict__ Wh, const fp16* __restrict__ Wl,
                                                   float* __restrict__ Cf) {
    extern __shared__ fp16 sg[];
    const int tid = threadIdx.x, lane = tid & 31, wid = tid >> 5;
    const int wm = (wid >> 2) * 64, wn = (wid & 3) * 32;
    const int m0 = blockIdx.y * 128, n0 = blockIdx.x * 128;

    GEMM_MAINLOOP(EE)

#pragma unroll
    for (int mi = 0; mi < 4; ++mi) {
        int r0 = m0 + wm + mi * 16 + (lane >> 2);
        int r1 = r0 + 8;
#pragma unroll
        for (int ni = 0; ni < 4; ++ni) {
            int col = n0 + wn + ni * 8 + 2 * (lane & 3);
            *(float2*)&Cf[(size_t)r0 * EE + col] = make_float2(acc[mi][ni][0], acc[mi][ni][1]);
            *(float2*)&Cf[(size_t)r1 * EE + col] = make_float2(acc[mi][ni][2], acc[mi][ni][3]);
        }
    }
}

// ---------------- differential flash attention + fused LayerNorm (64-key tiles) ----------------
// CTA: (64 q-rows, head-pair hp, batch b); 4 warps x 16 rows; 64-key tiles double-buffered.
// P = exp2 computed directly in fp16x2; row sums via all-ones B-fragment MMA.
// smem (fp16 elems): QH 0 (64x136), QL 8704; KV buf b at 17408+b*17408: K +0, V +8704.
#define SQH 0
#define SQL 8704
#define KVB 17408
#define FSM_ELEMS (17408 + 2 * 17408)
#define FSM_BYTES (FSM_ELEMS * 2)
#define ONES2 0x3C003C00u

__global__ __launch_bounds__(128, 2) void flash_kernel(const fp16* __restrict__ qh_, const fp16* __restrict__ ql_,
                                                       const fp16* __restrict__ k_, const fp16* __restrict__ v_,
                                                       const float* __restrict__ lng, const float* __restrict__ lnb,
                                                       fp16* __restrict__ o_) {
    extern __shared__ fp16 sm[];
    const int tid = threadIdx.x, lane = tid & 31, wid = tid >> 5;
    const int b = blockIdx.z, hp = blockIdx.y;
    const int q0 = blockIdx.x * 64;
    const int wrow = wid * 16;
    const float lam = g_lambda;

    auto copy_kv = [&](int kt, int bu) {
        int base = KVB + bu * 17408;
#pragma unroll
        for (int j = 0; j < 8; ++j) {
            int ch = tid + j * 128;
            int r = ch >> 4, s = (ch & 15) * 8;
            size_t src = (size_t)(b * NN + kt + r) * EE + hp * 128 + s;
            cpa16(s2u(&sm[base + r * 136 + s]), &k_[src]);
            cpa16(s2u(&sm[base + 8704 + r * 136 + s]), &v_[src]);
        }
    };

#pragma unroll
    for (int j = 0; j < 8; ++j) {
        int ch = tid + j * 128;
        int r = ch >> 4, s = (ch & 15) * 8;
        size_t src = (size_t)(b * NN + q0 + r) * EE + hp * 128 + s;
        cpa16(s2u(&sm[SQH + r * 136 + s]), &qh_[src]);
        cpa16(s2u(&sm[SQL + r * 136 + s]), &ql_[src]);
    }
    copy_kv(0, 0);
    CP_COMMIT;

    float acc0[16][4], acc1[16][4];
    float acS[2][4];   // row-sum accumulators: [half][0]=rowA, [half][2]=rowB
#pragma unroll
    for (int i = 0; i < 16; ++i)
#pragma unroll
        for (int j = 0; j < 4; ++j) { acc0[i][j] = 0.f; acc1[i][j] = 0.f; }
#pragma unroll
    for (int h2 = 0; h2 < 2; ++h2)
#pragma unroll
        for (int j = 0; j < 4; ++j) acS[h2][j] = 0.f;
    float mA[2], mB[2];
    mA[0] = mA[1] = mB[0] = mB[1] = -1e30f;

    int bu = 0;
    for (int kt = 0; kt < NN; kt += 64, bu ^= 1) {
        if (kt + 64 < NN) copy_kv(kt + 64, bu ^ 1);
        CP_COMMIT;
        CP_WAIT1;
        __syncthreads();
        const int lb = KVB + bu * 17408;

        uint32_t ph[2][4][4];
#pragma unroll
        for (int half = 0; half < 2; ++half) {
            float (*ac)[4] = half ? acc1 : acc0;
            float S[8][4];
#pragma unroll
            for (int i = 0; i < 8; ++i)
#pragma unroll
                for (int j = 0; j < 4; ++j) S[i][j] = 0.f;

            // S = (Qh + Ql) * K over d = half*64 .. +64 (log2e pre-folded into q)
#pragma unroll
            for (int kg = 0; kg < 4; ++kg) {
                int d0 = half * 64 + kg * 16 + (lane >> 4) * 8;
                uint32_t qh[4], ql[4];
                ldsm4(qh, s2u(&sm[SQH + (wrow + (lane & 15)) * 136 + d0]));
                ldsm4(ql, s2u(&sm[SQL + (wrow + (lane & 15)) * 136 + d0]));
#pragma unroll
                for (int p = 0; p < 4; ++p) {
                    uint32_t t[4];
                    ldsm4(t, s2u(&sm[lb + (p * 16 + (lane & 15)) * 136 + d0]));
                    mma16816(S[2 * p], qh, t[0], t[2]);
                    mma16816(S[2 * p], ql, t[0], t[2]);
                    mma16816(S[2 * p + 1], qh, t[1], t[3]);
                    mma16816(S[2 * p + 1], ql, t[1], t[3]);
                }
            }

            // online softmax, exp2 domain (rows: A = lane>>2, B = +8)
            float mxA = -1e30f, mxB = -1e30f;
#pragma unroll
            for (int ng = 0; ng < 8; ++ng) {
                mxA = fmaxf(mxA, fmaxf(S[ng][0], S[ng][1]));
                mxB = fmaxf(mxB, fmaxf(S[ng][2], S[ng][3]));
            }
            mxA = fmaxf(mxA, __shfl_xor_sync(0xffffffffu, mxA, 1));
            mxA = fmaxf(mxA, __shfl_xor_sync(0xffffffffu, mxA, 2));
            mxB = fmaxf(mxB, __shfl_xor_sync(0xffffffffu, mxB, 1));
            mxB = fmaxf(mxB, __shfl_xor_sync(0xffffffffu, mxB, 2));
            float nmA = fmaxf(mA[half], mxA), nmB = fmaxf(mB[half], mxB);
            float aA = ex2(mA[half] - nmA), aB = ex2(mB[half] - nmB);
            mA[half] = nmA; mB[half] = nmB;
            // rescale accumulators (including the row-sum columns)
#pragma unroll
            for (int ng = 0; ng < 16; ++ng) {
                ac[ng][0] *= aA; ac[ng][1] *= aA;
                ac[ng][2] *= aB; ac[ng][3] *= aB;
            }
            acS[half][0] *= aA; acS[half][1] *= aA;
            acS[half][2] *= aB; acS[half][3] *= aB;
            // P fragments: fused subtract + pack + exp2 in fp16x2
#pragma unroll
            for (int j = 0; j < 4; ++j) {
                ph[half][j][0] = exp2pack(S[2 * j][0] - nmA, S[2 * j][1] - nmA);
                ph[half][j][1] = exp2pack(S[2 * j][2] - nmB, S[2 * j][3] - nmB);
                ph[half][j][2] = exp2pack(S[2 * j + 1][0] - nmA, S[2 * j + 1][1] - nmA);
                ph[half][j][3] = exp2pack(S[2 * j + 1][2] - nmB, S[2 * j + 1][3] - nmB);
            }
            // row sums via all-ones B fragment (tensor core does the reduction)
#pragma unroll
            for (int j = 0; j < 4; ++j)
                mma16816(acS[half], ph[half][j], ONES2, ONES2);
        }

        // PV for both halves; V fragments loaded once
#pragma unroll
        for (int kg2 = 0; kg2 < 4; ++kg2) {
#pragma unroll
            for (int np = 0; np < 8; ++np) {
                uint32_t vf[4];
                int off = lb + 8704 + (kg2 * 16 + (lane & 15)) * 136 + np * 16 + (lane >> 4) * 8;
                ldsm4t(vf, s2u(&sm[off]));
                mma16816(acc0[2 * np], ph[0][kg2], vf[0], vf[1]);
                mma16816(acc0[2 * np + 1], ph[0][kg2], vf[2], vf[3]);
                mma16816(acc1[2 * np], ph[1][kg2], vf[0], vf[1]);
                mma16816(acc1[2 * np + 1], ph[1][kg2], vf[2], vf[3]);
            }
        }
        __syncthreads();
    }

    // Epilogue: o = acc0/l0 - lam*acc1/l1, per-head LayerNorm over 128 channels.
    float i0A = 1.f / acS[0][0], i0B = 1.f / acS[0][2];
    float i1A = lam / acS[1][0], i1B = lam / acS[1][2];
    float suA = 0.f, sqA = 0.f, suB = 0.f, sqB = 0.f;
#pragma unroll
    for (int ng = 0; ng < 16; ++ng) {
        float o0 = acc0[ng][0] * i0A - acc1[ng][0] * i1A;
        float o1 = acc0[ng][1] * i0A - acc1[ng][1] * i1A;
        float o2 = acc0[ng][2] * i0B - acc1[ng][2] * i1B;
        float o3 = acc0[ng][3] * i0B - acc1[ng][3] * i1B;
        acc0[ng][0] = o0; acc0[ng][1] = o1; acc0[ng][2] = o2; acc0[ng][3] = o3;
        suA += o0 + o1; sqA += o0 * o0 + o1 * o1;
        suB += o2 + o3; sqB += o2 * o2 + o3 * o3;
    }
    suA += __shfl_xor_sync(0xffffffffu, suA, 1); suA += __shfl_xor_sync(0xffffffffu, suA, 2);
    sqA += __shfl_xor_sync(0xffffffffu, sqA, 1); sqA += __shfl_xor_sync(0xffffffffu, sqA, 2);
    suB += __shfl_xor_sync(0xffffffffu, suB, 1); suB += __shfl_xor_sync(0xffffffffu, suB, 2);
    sqB += __shfl_xor_sync(0xffffffffu, sqB, 1); sqB += __shfl_xor_sync(0xffffffffu, sqB, 2);
    float muA = suA * (1.f / 128.f), muB = suB * (1.f / 128.f);
    float rsA = rsqrtf(sqA * (1.f / 128.f) - muA * muA + 1e-5f);
    float rsB = rsqrtf(sqB * (1.f / 128.f) - muB * muB + 1e-5f);

    int rA = b * NN + q0 + wrow + (lane >> 2);
    int rB = rA + 8;
#pragma unroll
    for (int ng = 0; ng < 16; ++ng) {
        int col = ng * 8 + 2 * (lane & 3);
        float g0 = lng[col], g1 = lng[col + 1];
        float b0 = lnb[col], b1 = lnb[col + 1];
        float y0 = (acc0[ng][0] - muA) * rsA * g0 + b0;
        float y1 = (acc0[ng][1] - muA) * rsA * g1 + b1;
        float y2 = (acc0[ng][2] - muB) * rsB * g0 + b0;
        float y3 = (acc0[ng][3] - muB) * rsB * g1 + b1;
        size_t dA = (size_t)rA * EE + hp * 128 + col;
        size_t dB = (size_t)rB * EE + hp * 128 + col;
        *(uint32_t*)&o_[dA] = pack2h(y0, y1);
        *(uint32_t*)&o_[dB] = pack2h(y2, y3);
    }
}

// ---------------------------------------------------------------------------
extern "C" void kernel_launch(void* const* d_in, const int* in_sizes, int n_in,
                              void* d_out, int out_size) {
    const float* x   = (const float*)d_in[0];
    const float* Wq  = (const float*)d_in[1];
    const float* Wk  = (const float*)d_in[2];
    const float* Wv  = (const float*)d_in[3];
    const float* Wo  = (const float*)d_in[4];
    const float* lq1 = (const float*)d_in[5];
    const float* lk1 = (const float*)d_in[6];
    const float* lq2 = (const float*)d_in[7];
    const float* lk2 = (const float*)d_in[8];
    const float* lng = (const float*)d_in[9];
    const float* lnb = (const float*)d_in[10];
    float* out = (float*)d_out;

    fp16 *wqkvh, *wqkvl, *woh, *wol, *x16, *qh, *ql, *kk, *vv, *a16;
    cudaGetSymbolAddress((void**)&wqkvh, g_wqkvh);
    cudaGetSymbolAddress((void**)&wqkvl, g_wqkvl);
    cudaGetSymbolAddress((void**)&woh, g_woh);
    cudaGetSymbolAddress((void**)&wol, g_wol);
    cudaGetSymbolAddress((void**)&x16, g_x16);
    cudaGetSymbolAddress((void**)&qh, g_qh);
    cudaGetSymbolAddress((void**)&ql, g_ql);
    cudaGetSymbolAddress((void**)&kk, g_k);
    cudaGetSymbolAddress((void**)&vv, g_v);
    cudaGetSymbolAddress((void**)&a16, g_a16);

    wsplit_kernel<<<dim3(1024, 4), 256>>>(Wq, Wk, Wv, Wo);
    xround_kernel<<<4096, 256>>>(x);
    lambda_kernel<<<1, 32>>>(lq1, lk1, lq2, lk2);

    cudaFuncSetAttribute(qkv_gemm, cudaFuncAttributeMaxDynamicSharedMemorySize, GSM_BYTES);
    cudaFuncSetAttribute(out_gemm, cudaFuncAttributeMaxDynamicSharedMemorySize, GSM_BYTES);
    cudaFuncSetAttribute(flash_kernel, cudaFuncAttributeMaxDynamicSharedMemorySize, FSM_BYTES);

    const float LOG2E = 1.4426950408889634f;
    qkv_gemm<<<dim3(24, 32), 256, GSM_BYTES>>>(x16, wqkvh, wqkvl, qh, ql, kk, vv, 0.125f * LOG2E);

    dim3 fg(NN / 64, HH, BB);  // (32, 8, 2)
    flash_kernel<<<fg, 128, FSM_BYTES>>>(qh, ql, kk, vv, lng, lnb, a16);

    out_gemm<<<dim3(8, 32), 256, GSM_BYTES>>>(a16, woh, wol, out);
}